// round 7
// baseline (speedup 1.0000x reference)
#include <cuda_runtime.h>
#include <mma.h>
#include <math.h>

using namespace nvcuda;

#define MAXM 400000

// row-major padded scratch
__device__ float g_taf[(size_t)MAXM * 56 + 1024];   // [M][56], cols 51..55 = 0
__device__ float g_tafm[(size_t)MAXM * 48 + 1024];  // [M][48]
__device__ float g_pf[MAXM + 1024];
__device__ float g_mf[MAXM + 1024];

__device__ __forceinline__ float sigmoidf_(float x) { return 1.f / (1.f + expf(-x)); }

// ================= builder =================
__global__ __launch_bounds__(256)
void build_kernel(const float* __restrict__ cam,
                  const float* __restrict__ anchors,
                  const float* __restrict__ scales,
                  const float* __restrict__ afeat,
                  const float* __restrict__ tfeat,
                  const float* __restrict__ factors,
                  const int* __restrict__ vis,
                  const int* __restrict__ knn,
                  float* __restrict__ out, int M)
{
    int m = blockIdx.x * 256 + threadIdx.x;
    if (m >= M) return;
    int idx = vis[m];

    float a[56];
    const float4* fp = reinterpret_cast<const float4*>(afeat + (long long)idx * 32);
    #pragma unroll
    for (int q = 0; q < 8; q++) {
        float4 v = __ldg(fp + q);
        a[4*q+0] = v.x; a[4*q+1] = v.y; a[4*q+2] = v.z; a[4*q+3] = v.w;
    }
    float ax = __ldg(anchors + (long long)idx * 3 + 0);
    float ay = __ldg(anchors + (long long)idx * 3 + 1);
    float az = __ldg(anchors + (long long)idx * 3 + 2);
    float vx = ax - cam[3], vy = ay - cam[7], vz = az - cam[11];
    float nrm = sqrtf(vx*vx + vy*vy + vz*vz);
    float inv = 1.f / fmaxf(nrm, 1e-8f);
    a[32] = vx * inv; a[33] = vy * inv; a[34] = vz * inv;

    float4 fc = __ldg(reinterpret_cast<const float4*>(factors + (long long)idx * 4));
    float tff = fc.x, mf = fc.y, kf = fc.z, pf = fc.w;

    const float4* tp = reinterpret_cast<const float4*>(tfeat + (long long)idx * 256 + 112);
    #pragma unroll
    for (int q = 0; q < 4; q++) {
        float4 v = __ldg(tp + q);
        a[35+4*q+0] = v.x*tff; a[35+4*q+1] = v.y*tff;
        a[35+4*q+2] = v.z*tff; a[35+4*q+3] = v.w*tff;
    }
    a[51] = 0.f; a[52] = 0.f; a[53] = 0.f; a[54] = 0.f; a[55] = 0.f;

    float4* tr = reinterpret_cast<float4*>(g_taf + (size_t)m * 56);
    #pragma unroll
    for (int q = 0; q < 14; q++)
        tr[q] = make_float4(a[4*q], a[4*q+1], a[4*q+2], a[4*q+3]);
    g_pf[m] = pf;
    g_mf[m] = mf;

    // ---- knn mix -> taf_ ----
    float facc[48];
    #pragma unroll
    for (int i = 0; i < 48; i++) facc[i] = 0.f;
    const int* kp = knn + (long long)idx * 6;
    #pragma unroll 1
    for (int nb = 0; nb < 6; nb++) {
        int nidx = __ldg(kp + nb);
        const float4* nf = reinterpret_cast<const float4*>(afeat + (long long)nidx * 32);
        #pragma unroll
        for (int q = 0; q < 8; q++) {
            float4 v = __ldg(nf + q);
            facc[4*q+0] += v.x; facc[4*q+1] += v.y;
            facc[4*q+2] += v.z; facc[4*q+3] += v.w;
        }
        const float4* nt = reinterpret_cast<const float4*>(tfeat + (long long)nidx * 256 + 112);
        #pragma unroll
        for (int q = 0; q < 4; q++) {
            float4 v = __ldg(nt + q);
            facc[32+4*q+0] += v.x; facc[32+4*q+1] += v.y;
            facc[32+4*q+2] += v.z; facc[32+4*q+3] += v.w;
        }
    }
    float wk = (1.f - kf) * (1.f / 6.f);
    float b[48];
    #pragma unroll
    for (int i = 0; i < 32; i++) b[i] = kf * a[i] + wk * facc[i];
    #pragma unroll
    for (int c = 0; c < 16; c++) b[32+c] = kf * a[35+c] + wk * facc[32+c];

    float4* mr = reinterpret_cast<float4*>(g_tafm + (size_t)m * 48);
    #pragma unroll
    for (int q = 0; q < 12; q++)
        mr[q] = make_float4(b[4*q], b[4*q+1], b[4*q+2], b[4*q+3]);

    // ---- epilogue columns of out_m ----
    float* om = out + (long long)M * 110 + (long long)m * 50;
    const float* sp = scales + (long long)idx * 6;
    om[37] = expf(__ldg(sp + 0));
    om[38] = expf(__ldg(sp + 1));
    om[39] = expf(__ldg(sp + 2));
    om[40] = expf(__ldg(sp + 3)) * pf;
    om[41] = expf(__ldg(sp + 4)) * pf;
    om[42] = expf(__ldg(sp + 5)) * pf;
    om[43] = tff; om[44] = mf; om[45] = kf; om[46] = pf;
    om[47] = ax; om[48] = ay; om[49] = az;
}

// ================= wmma tf32 MLP kernel =================
// 128 points/block, 8 warps. smem: W1[KP*64] W2[64*N2P] B1[64] B2[N2Pp] XC[128*XDIM] H[128*64]
// ACT: 0=op(tanh*pf) 1=col(sigmoid) 2=cov(raw) 3=mot(*mf)
template <int KP, int KIN, int N2P, int NOUT, int ACT>
__global__ __launch_bounds__(256, 2)
void mlp_wmma_kernel(const float* __restrict__ xin,
                     const float* __restrict__ w1g, const float* __restrict__ b1g,
                     const float* __restrict__ w2g, const float* __restrict__ b2g,
                     const float* __restrict__ scl,
                     float* __restrict__ out, int M)
{
    constexpr int XDIM = (KP > N2P) ? KP : N2P;
    constexpr int N2Pp = (N2P + 7) & ~7;
    constexpr int OW1 = 0;
    constexpr int OW2 = OW1 + KP * 64;
    constexpr int OB1 = OW2 + 64 * N2P;
    constexpr int OB2 = OB1 + 64;
    constexpr int OXC = OB2 + N2Pp;       // union: X tile then C2 tile
    constexpr int OH  = OXC + 128 * XDIM;

    extern __shared__ float S[];
    const int tid = threadIdx.x;
    const int warp = tid >> 5;
    const size_t bm0 = (size_t)blockIdx.x * 128;

    // ---- stage weights ----
    for (int i = tid; i < KP * 64; i += 256) {
        int row = i >> 6;
        S[OW1 + i] = (row < KIN) ? w1g[i] : 0.f;
    }
    for (int i = tid; i < 64 * N2P; i += 256) {
        int j = i / N2P, k = i - j * N2P;
        S[OW2 + i] = (k < NOUT) ? w2g[j * NOUT + k] : 0.f;
    }
    if (tid < 64) {
        float acc = b1g[tid];
        if (ACT == 3) {
            #pragma unroll
            for (int t = 0; t < 8; t++) {
                float ang = exp2f((float)t) * 1.5707963267948966f;
                acc = fmaf(sinf(ang), w1g[(48 + t) * 64 + tid], acc);
                acc = fmaf(cosf(ang), w1g[(56 + t) * 64 + tid], acc);
            }
        }
        S[OB1 + tid] = acc;
    }
    if (tid < N2Pp) S[OB2 + tid] = (tid < NOUT) ? b2g[tid] : 0.f;

    // ---- stage X tile [128 x KP] (rows >= M zeroed) ----
    {
        const size_t base = bm0 * KP;
        const size_t lim = (size_t)M * KP;
        for (int t = tid * 4; t < 128 * KP; t += 1024) {
            float4 v = (base + t + 3 < lim)
                ? __ldg(reinterpret_cast<const float4*>(xin + base + t))
                : make_float4(0.f, 0.f, 0.f, 0.f);
            *reinterpret_cast<float4*>(S + OXC + t) = v;
        }
    }
    __syncthreads();

    // ---- GEMM1: H[128x64] = X[128xKP] @ W1[KPx64] ----
    {
        wmma::fragment<wmma::accumulator, 16, 16, 8, float> c[4];
        #pragma unroll
        for (int n = 0; n < 4; n++) wmma::fill_fragment(c[n], 0.f);
        #pragma unroll 1
        for (int k = 0; k < KP / 8; k++) {
            wmma::fragment<wmma::matrix_a, 16, 16, 8, wmma::precision::tf32, wmma::row_major> af;
            wmma::load_matrix_sync(af, S + OXC + warp * 16 * KP + k * 8, KP);
            #pragma unroll
            for (int i = 0; i < af.num_elements; i++) af.x[i] = wmma::__float_to_tf32(af.x[i]);
            #pragma unroll
            for (int n = 0; n < 4; n++) {
                wmma::fragment<wmma::matrix_b, 16, 16, 8, wmma::precision::tf32, wmma::row_major> bf;
                wmma::load_matrix_sync(bf, S + OW1 + k * 8 * 64 + n * 16, 64);
                #pragma unroll
                for (int i = 0; i < bf.num_elements; i++) bf.x[i] = wmma::__float_to_tf32(bf.x[i]);
                wmma::mma_sync(c[n], af, bf, c[n]);
            }
        }
        #pragma unroll
        for (int n = 0; n < 4; n++)
            wmma::store_matrix_sync(S + OH + warp * 16 * 64 + n * 16, c[n], 64, wmma::mem_row_major);
    }
    __syncthreads();

    // ---- bias + relu on H ----
    for (int t = tid; t < 128 * 64; t += 256) {
        int col = t & 63;
        S[OH + t] = fmaxf(S[OH + t] + S[OB1 + col], 0.f);
    }
    __syncthreads();

    // ---- GEMM2: C2[128xN2P] = H @ W2[64xN2P] (C2 overwrites X region) ----
    {
        constexpr int NF = N2P / 16;
        wmma::fragment<wmma::accumulator, 16, 16, 8, float> c[NF];
        #pragma unroll
        for (int n = 0; n < NF; n++) wmma::fill_fragment(c[n], 0.f);
        #pragma unroll 1
        for (int k = 0; k < 8; k++) {
            wmma::fragment<wmma::matrix_a, 16, 16, 8, wmma::precision::tf32, wmma::row_major> af;
            wmma::load_matrix_sync(af, S + OH + warp * 16 * 64 + k * 8, 64);
            #pragma unroll
            for (int i = 0; i < af.num_elements; i++) af.x[i] = wmma::__float_to_tf32(af.x[i]);
            #pragma unroll
            for (int n = 0; n < NF; n++) {
                wmma::fragment<wmma::matrix_b, 16, 16, 8, wmma::precision::tf32, wmma::row_major> bf;
                wmma::load_matrix_sync(bf, S + OW2 + k * 8 * N2P + n * 16, N2P);
                #pragma unroll
                for (int i = 0; i < bf.num_elements; i++) bf.x[i] = wmma::__float_to_tf32(bf.x[i]);
                wmma::mma_sync(c[n], af, bf, c[n]);
            }
        }
        __syncthreads();   // X region fully consumed by all warps before overwrite
        #pragma unroll
        for (int n = 0; n < NF; n++)
            wmma::store_matrix_sync(S + OXC + warp * 16 * N2P + n * 16, c[n], N2P, wmma::mem_row_major);
    }
    __syncthreads();

    // ---- epilogue: 128 threads, one point each ----
    if (tid < 128) {
        size_t m = bm0 + tid;
        if (m < (size_t)M) {
            const float* c2 = S + OXC + tid * N2P;
            if (ACT == 0) {
                float pf = scl[m];
                float* omk = out + m * 110;
                #pragma unroll
                for (int k = 0; k < 10; k++)
                    omk[k * 11] = tanhf(c2[k] + S[OB2 + k]) * pf;
            } else if (ACT == 1) {
                float* omk = out + m * 110;
                #pragma unroll
                for (int k = 0; k < 30; k++) {
                    int kd = k / 3;
                    omk[kd * 11 + 1 + (k - kd * 3)] = sigmoidf_(c2[k] + S[OB2 + k]);
                }
            } else if (ACT == 2) {
                float* omk = out + m * 110;
                #pragma unroll
                for (int k = 0; k < 70; k++) {
                    int kd = k / 7;
                    omk[kd * 11 + 4 + (k - kd * 7)] = c2[k] + S[OB2 + k];
                }
            } else {
                float mf = scl[m];
                float* om = out + (size_t)M * 110 + m * 50;
                #pragma unroll
                for (int k = 0; k < 37; k++)
                    om[k] = (c2[k] + S[OB2 + k]) * mf;
            }
        }
    }
}

// ================= launch =================
extern "C" void kernel_launch(void* const* d_in, const int* in_sizes, int n_in,
                              void* d_out, int out_size)
{
    const float* cam     = (const float*)d_in[0];
    const float* anchors = (const float*)d_in[1];
    const float* scales  = (const float*)d_in[2];
    const float* afeat   = (const float*)d_in[3];
    const float* tfeat   = (const float*)d_in[4];
    const float* factors = (const float*)d_in[5];
    const float* op_w1   = (const float*)d_in[6];
    const float* op_b1   = (const float*)d_in[7];
    const float* op_w2   = (const float*)d_in[8];
    const float* op_b2   = (const float*)d_in[9];
    const float* col_w1  = (const float*)d_in[10];
    const float* col_b1  = (const float*)d_in[11];
    const float* col_w2  = (const float*)d_in[12];
    const float* col_b2  = (const float*)d_in[13];
    const float* cov_w1  = (const float*)d_in[14];
    const float* cov_b1  = (const float*)d_in[15];
    const float* cov_w2  = (const float*)d_in[16];
    const float* cov_b2  = (const float*)d_in[17];
    const float* mot_w1  = (const float*)d_in[18];
    const float* mot_b1  = (const float*)d_in[19];
    const float* mot_w2  = (const float*)d_in[20];
    const float* mot_b2  = (const float*)d_in[21];
    const int*   vis     = (const int*)d_in[22];
    const int*   knn     = (const int*)d_in[23];

    int M = in_sizes[22];
    float* out = (float*)d_out;

    float *taf, *tafm, *pf, *mf;
    cudaGetSymbolAddress((void**)&taf,  g_taf);
    cudaGetSymbolAddress((void**)&tafm, g_tafm);
    cudaGetSymbolAddress((void**)&pf,   g_pf);
    cudaGetSymbolAddress((void**)&mf,   g_mf);

    const int GB = (M + 255) / 256;
    const int GW = (M + 127) / 128;

    auto smem_bytes = [](int KP, int N2P) {
        int XDIM = (KP > N2P) ? KP : N2P;
        int N2Pp = (N2P + 7) & ~7;
        return (KP * 64 + 64 * N2P + 64 + N2Pp + 128 * XDIM + 128 * 64) * 4;
    };
    int smem_op  = smem_bytes(56, 16);
    int smem_col = smem_bytes(56, 32);
    int smem_cov = smem_bytes(56, 80);
    int smem_mot = smem_bytes(48, 48);

    cudaFuncSetAttribute((const void*)mlp_wmma_kernel<56,51,16,10,0>, cudaFuncAttributeMaxDynamicSharedMemorySize, smem_op);
    cudaFuncSetAttribute((const void*)mlp_wmma_kernel<56,51,32,30,1>, cudaFuncAttributeMaxDynamicSharedMemorySize, smem_col);
    cudaFuncSetAttribute((const void*)mlp_wmma_kernel<56,51,80,70,2>, cudaFuncAttributeMaxDynamicSharedMemorySize, smem_cov);
    cudaFuncSetAttribute((const void*)mlp_wmma_kernel<48,48,48,37,3>, cudaFuncAttributeMaxDynamicSharedMemorySize, smem_mot);

    build_kernel<<<GB, 256>>>(cam, anchors, scales, afeat, tfeat, factors, vis, knn, out, M);
    mlp_wmma_kernel<56,51,16,10,0><<<GW, 256, smem_op >>>(taf,  op_w1,  op_b1,  op_w2,  op_b2,  pf, out, M);
    mlp_wmma_kernel<56,51,32,30,1><<<GW, 256, smem_col>>>(taf,  col_w1, col_b1, col_w2, col_b2, pf, out, M);
    mlp_wmma_kernel<56,51,80,70,2><<<GW, 256, smem_cov>>>(taf,  cov_w1, cov_b1, cov_w2, cov_b2, pf, out, M);
    mlp_wmma_kernel<48,48,48,37,3><<<GW, 256, smem_mot>>>(tafm, mot_w1, mot_b1, mot_w2, mot_b2, mf, out, M);
}

// round 8
// speedup vs baseline: 1.5126x; 1.5126x over previous
#include <cuda_runtime.h>
#include <mma.h>
#include <math.h>

using namespace nvcuda;

#define MAXM 400000

// row-major, pre-rounded-to-tf32 scratch (pad covers tail tile reads)
__device__ __align__(256) float g_taf[(size_t)MAXM * 56 + 1024];   // [M][56], cols 51..55 = 0
__device__ __align__(256) float g_tafm[(size_t)MAXM * 48 + 1024];  // [M][48]
__device__ float g_pf[MAXM + 1024];
__device__ float g_mf[MAXM + 1024];

__device__ __forceinline__ float sigmoidf_(float x) { return 1.f / (1.f + expf(-x)); }
__device__ __forceinline__ float tf32r(float x) { return wmma::__float_to_tf32(x); }

// ================= builder =================
__global__ __launch_bounds__(256)
void build_kernel(const float* __restrict__ cam,
                  const float* __restrict__ anchors,
                  const float* __restrict__ scales,
                  const float* __restrict__ afeat,
                  const float* __restrict__ tfeat,
                  const float* __restrict__ factors,
                  const int* __restrict__ vis,
                  const int* __restrict__ knn,
                  float* __restrict__ out, int M)
{
    int m = blockIdx.x * 256 + threadIdx.x;
    if (m >= M) return;
    int idx = vis[m];

    float a[56];
    const float4* fp = reinterpret_cast<const float4*>(afeat + (long long)idx * 32);
    #pragma unroll
    for (int q = 0; q < 8; q++) {
        float4 v = __ldg(fp + q);
        a[4*q+0] = v.x; a[4*q+1] = v.y; a[4*q+2] = v.z; a[4*q+3] = v.w;
    }
    float ax = __ldg(anchors + (long long)idx * 3 + 0);
    float ay = __ldg(anchors + (long long)idx * 3 + 1);
    float az = __ldg(anchors + (long long)idx * 3 + 2);
    float vx = ax - cam[3], vy = ay - cam[7], vz = az - cam[11];
    float nrm = sqrtf(vx*vx + vy*vy + vz*vz);
    float inv = 1.f / fmaxf(nrm, 1e-8f);
    a[32] = vx * inv; a[33] = vy * inv; a[34] = vz * inv;

    float4 fc = __ldg(reinterpret_cast<const float4*>(factors + (long long)idx * 4));
    float tff = fc.x, mf = fc.y, kf = fc.z, pf = fc.w;

    const float4* tp = reinterpret_cast<const float4*>(tfeat + (long long)idx * 256 + 112);
    #pragma unroll
    for (int q = 0; q < 4; q++) {
        float4 v = __ldg(tp + q);
        a[35+4*q+0] = v.x*tff; a[35+4*q+1] = v.y*tff;
        a[35+4*q+2] = v.z*tff; a[35+4*q+3] = v.w*tff;
    }
    a[51] = 0.f; a[52] = 0.f; a[53] = 0.f; a[54] = 0.f; a[55] = 0.f;

    // pre-round to tf32 so the MLP kernels can skip per-fragment cvt
    float4* tr = reinterpret_cast<float4*>(g_taf + (size_t)m * 56);
    #pragma unroll
    for (int q = 0; q < 14; q++)
        tr[q] = make_float4(tf32r(a[4*q]), tf32r(a[4*q+1]), tf32r(a[4*q+2]), tf32r(a[4*q+3]));
    g_pf[m] = pf;
    g_mf[m] = mf;

    // ---- knn mix -> taf_ ----
    float facc[48];
    #pragma unroll
    for (int i = 0; i < 48; i++) facc[i] = 0.f;
    const int* kp = knn + (long long)idx * 6;
    #pragma unroll 1
    for (int nb = 0; nb < 6; nb++) {
        int nidx = __ldg(kp + nb);
        const float4* nf = reinterpret_cast<const float4*>(afeat + (long long)nidx * 32);
        #pragma unroll
        for (int q = 0; q < 8; q++) {
            float4 v = __ldg(nf + q);
            facc[4*q+0] += v.x; facc[4*q+1] += v.y;
            facc[4*q+2] += v.z; facc[4*q+3] += v.w;
        }
        const float4* nt = reinterpret_cast<const float4*>(tfeat + (long long)nidx * 256 + 112);
        #pragma unroll
        for (int q = 0; q < 4; q++) {
            float4 v = __ldg(nt + q);
            facc[32+4*q+0] += v.x; facc[32+4*q+1] += v.y;
            facc[32+4*q+2] += v.z; facc[32+4*q+3] += v.w;
        }
    }
    float wk = (1.f - kf) * (1.f / 6.f);
    float b[48];
    #pragma unroll
    for (int i = 0; i < 32; i++) b[i] = kf * a[i] + wk * facc[i];
    #pragma unroll
    for (int c = 0; c < 16; c++) b[32+c] = kf * a[35+c] + wk * facc[32+c];

    float4* mr = reinterpret_cast<float4*>(g_tafm + (size_t)m * 48);
    #pragma unroll
    for (int q = 0; q < 12; q++)
        mr[q] = make_float4(tf32r(b[4*q]), tf32r(b[4*q+1]), tf32r(b[4*q+2]), tf32r(b[4*q+3]));

    // ---- epilogue columns of out_m (full fp32) ----
    float* om = out + (long long)M * 110 + (long long)m * 50;
    const float* sp = scales + (long long)idx * 6;
    om[37] = expf(__ldg(sp + 0));
    om[38] = expf(__ldg(sp + 1));
    om[39] = expf(__ldg(sp + 2));
    om[40] = expf(__ldg(sp + 3)) * pf;
    om[41] = expf(__ldg(sp + 4)) * pf;
    om[42] = expf(__ldg(sp + 5)) * pf;
    om[43] = tff; om[44] = mf; om[45] = kf; om[46] = pf;
    om[47] = ax; om[48] = ay; om[49] = az;
}

// ================= persistent warp-autonomous wmma MLP =================
// Each warp owns a 16-point tile; no block syncs after weight staging.
// smem: W1[KP*64] W2[64*N2P] B1rep[16*64] B2rep[16*N2P] + per-warp 16*RSTR slab
// ACT: 0=op(tanh*pf) 1=col(sigmoid) 2=cov(raw) 3=mot(*mf)
template <int KP, int KIN, int N2P, int NOUT, int ACT>
__global__ __launch_bounds__(256, 2)
void mlp_wmma_kernel(const float* __restrict__ xin,
                     const float* __restrict__ w1g, const float* __restrict__ b1g,
                     const float* __restrict__ w2g, const float* __restrict__ b2g,
                     const float* __restrict__ scl,
                     float* __restrict__ out, int M)
{
    constexpr int RSTR = (N2P + 8 > 72) ? N2P + 8 : 72;  // per-warp slab row stride
    constexpr int NF2 = N2P / 16;
    constexpr int OW1 = 0;
    constexpr int OW2 = OW1 + KP * 64;
    constexpr int OB1R = OW2 + 64 * N2P;
    constexpr int OB2R = OB1R + 16 * 64;
    constexpr int OWRP = OB2R + 16 * N2P;

    extern __shared__ float S[];
    const int tid = threadIdx.x;
    const int warp = tid >> 5;
    const int lane = tid & 31;

    // ---- stage weights (pre-rounded), once per block ----
    for (int i = tid; i < KP * 64; i += 256) {
        int row = i >> 6;
        S[OW1 + i] = (row < KIN) ? tf32r(w1g[i]) : 0.f;
    }
    for (int i = tid; i < 64 * N2P; i += 256) {
        int j = i / N2P, k = i - j * N2P;
        S[OW2 + i] = (k < NOUT) ? tf32r(w2g[j * NOUT + k]) : 0.f;
    }
    if (tid < 64) {
        float acc = b1g[tid];
        if (ACT == 3) {
            #pragma unroll
            for (int t = 0; t < 8; t++) {
                float ang = exp2f((float)t) * 1.5707963267948966f;
                acc = fmaf(sinf(ang), w1g[(48 + t) * 64 + tid], acc);
                acc = fmaf(cosf(ang), w1g[(56 + t) * 64 + tid], acc);
            }
        }
        S[OB1R + tid] = acc;
    }
    if (tid < N2P) S[OB2R + tid] = (tid < NOUT) ? b2g[tid] : 0.f;
    __syncthreads();
    // replicate bias rows 1..15 (accumulator-fragment init trick)
    for (int i = tid; i < 16 * 64; i += 256)
        if (i >= 64) S[OB1R + i] = S[OB1R + (i & 63)];
    for (int i = tid; i < 16 * N2P; i += 256)
        if (i >= N2P) S[OB2R + i] = S[OB2R + (i % N2P)];
    __syncthreads();

    float* Hp = S + OWRP + warp * 16 * RSTR;
    const int tiles = (M + 15) >> 4;

    for (int t = blockIdx.x * 8 + warp; t < tiles; t += gridDim.x * 8) {
        const float* aptr = xin + (size_t)t * 16 * KP;

        // ---- GEMM1: [16xKP] @ [KPx64], bias preloaded as C ----
        wmma::fragment<wmma::accumulator, 16, 16, 8, float> c1[4];
        #pragma unroll
        for (int n = 0; n < 4; n++)
            wmma::load_matrix_sync(c1[n], S + OB1R + n * 16, 64, wmma::mem_row_major);
        #pragma unroll 1
        for (int k = 0; k < KP / 8; k++) {
            wmma::fragment<wmma::matrix_a, 16, 16, 8, wmma::precision::tf32, wmma::row_major> af;
            wmma::load_matrix_sync(af, aptr + k * 8, KP);   // gmem, pre-rounded
            #pragma unroll
            for (int n = 0; n < 4; n++) {
                wmma::fragment<wmma::matrix_b, 16, 16, 8, wmma::precision::tf32, wmma::row_major> bf;
                wmma::load_matrix_sync(bf, S + OW1 + k * 8 * 64 + n * 16, 64);
                wmma::mma_sync(c1[n], af, bf, c1[n]);
            }
        }
        // relu + tf32-round on accumulator regs (position-independent), store H
        #pragma unroll
        for (int n = 0; n < 4; n++) {
            #pragma unroll
            for (int i = 0; i < c1[n].num_elements; i++)
                c1[n].x[i] = tf32r(fmaxf(c1[n].x[i], 0.f));
            wmma::store_matrix_sync(Hp + n * 16, c1[n], RSTR, wmma::mem_row_major);
        }
        __syncwarp();

        // ---- GEMM2: [16x64] @ [64xN2P], bias preloaded as C ----
        wmma::fragment<wmma::accumulator, 16, 16, 8, float> c2[NF2];
        #pragma unroll
        for (int n = 0; n < NF2; n++)
            wmma::load_matrix_sync(c2[n], S + OB2R + n * 16, N2P, wmma::mem_row_major);
        #pragma unroll 1
        for (int k = 0; k < 8; k++) {
            wmma::fragment<wmma::matrix_a, 16, 16, 8, wmma::precision::tf32, wmma::row_major> af;
            wmma::load_matrix_sync(af, Hp + k * 8, RSTR);
            #pragma unroll
            for (int n = 0; n < NF2; n++) {
                wmma::fragment<wmma::matrix_b, 16, 16, 8, wmma::precision::tf32, wmma::row_major> bf;
                wmma::load_matrix_sync(bf, S + OW2 + k * 8 * N2P + n * 16, N2P);
                wmma::mma_sync(c2[n], af, bf, c2[n]);
            }
        }
        __syncwarp();   // H fully consumed; overwrite slab with C2
        #pragma unroll
        for (int n = 0; n < NF2; n++)
            wmma::store_matrix_sync(Hp + n * 16, c2[n], RSTR, wmma::mem_row_major);
        __syncwarp();

        // ---- epilogue: 2 lanes per point ----
        {
            int p = lane >> 1, half = lane & 1;
            size_t m = (size_t)t * 16 + p;
            if (m < (size_t)M) {
                const float* c2r = Hp + p * RSTR;
                if (ACT == 0) {
                    float pf = __ldg(scl + m);
                    float* omk = out + m * 110;
                    #pragma unroll
                    for (int k = half * 5; k < half * 5 + 5; k++)
                        omk[k * 11] = tanhf(c2r[k]) * pf;
                } else if (ACT == 1) {
                    float* omk = out + m * 110;
                    #pragma unroll
                    for (int k = half * 15; k < half * 15 + 15; k++) {
                        int kd = k / 3;
                        omk[kd * 11 + 1 + (k - kd * 3)] = sigmoidf_(c2r[k]);
                    }
                } else if (ACT == 2) {
                    float* omk = out + m * 110;
                    #pragma unroll
                    for (int k = half * 35; k < half * 35 + 35; k++) {
                        int kd = k / 7;
                        omk[kd * 11 + 4 + (k - kd * 7)] = c2r[k];
                    }
                } else {
                    float mf = __ldg(scl + m);
                    float* om = out + (size_t)M * 110 + m * 50;
                    int k0 = half ? 19 : 0, k1 = half ? 37 : 19;
                    for (int k = k0; k < k1; k++)
                        om[k] = c2r[k] * mf;
                }
            }
        }
        __syncwarp();   // slab reuse next iteration
    }
}

// ================= launch =================
extern "C" void kernel_launch(void* const* d_in, const int* in_sizes, int n_in,
                              void* d_out, int out_size)
{
    const float* cam     = (const float*)d_in[0];
    const float* anchors = (const float*)d_in[1];
    const float* scales  = (const float*)d_in[2];
    const float* afeat   = (const float*)d_in[3];
    const float* tfeat   = (const float*)d_in[4];
    const float* factors = (const float*)d_in[5];
    const float* op_w1   = (const float*)d_in[6];
    const float* op_b1   = (const float*)d_in[7];
    const float* op_w2   = (const float*)d_in[8];
    const float* op_b2   = (const float*)d_in[9];
    const float* col_w1  = (const float*)d_in[10];
    const float* col_b1  = (const float*)d_in[11];
    const float* col_w2  = (const float*)d_in[12];
    const float* col_b2  = (const float*)d_in[13];
    const float* cov_w1  = (const float*)d_in[14];
    const float* cov_b1  = (const float*)d_in[15];
    const float* cov_w2  = (const float*)d_in[16];
    const float* cov_b2  = (const float*)d_in[17];
    const float* mot_w1  = (const float*)d_in[18];
    const float* mot_b1  = (const float*)d_in[19];
    const float* mot_w2  = (const float*)d_in[20];
    const float* mot_b2  = (const float*)d_in[21];
    const int*   vis     = (const int*)d_in[22];
    const int*   knn     = (const int*)d_in[23];

    int M = in_sizes[22];
    float* out = (float*)d_out;

    float *taf, *tafm, *pf, *mf;
    cudaGetSymbolAddress((void**)&taf,  g_taf);
    cudaGetSymbolAddress((void**)&tafm, g_tafm);
    cudaGetSymbolAddress((void**)&pf,   g_pf);
    cudaGetSymbolAddress((void**)&mf,   g_mf);

    const int GB = (M + 255) / 256;
    const int GP = 296;   // persistent: 2 blocks/SM * 148 SMs

    auto smem_bytes = [](int KP, int N2P) {
        int RSTR = (N2P + 8 > 72) ? N2P + 8 : 72;
        return (KP * 64 + 64 * N2P + 16 * 64 + 16 * N2P + 8 * 16 * RSTR) * 4;
    };
    int smem_op  = smem_bytes(56, 16);
    int smem_col = smem_bytes(56, 32);
    int smem_cov = smem_bytes(56, 80);
    int smem_mot = smem_bytes(48, 48);

    cudaFuncSetAttribute((const void*)mlp_wmma_kernel<56,51,16,10,0>, cudaFuncAttributeMaxDynamicSharedMemorySize, smem_op);
    cudaFuncSetAttribute((const void*)mlp_wmma_kernel<56,51,32,30,1>, cudaFuncAttributeMaxDynamicSharedMemorySize, smem_col);
    cudaFuncSetAttribute((const void*)mlp_wmma_kernel<56,51,80,70,2>, cudaFuncAttributeMaxDynamicSharedMemorySize, smem_cov);
    cudaFuncSetAttribute((const void*)mlp_wmma_kernel<48,48,48,37,3>, cudaFuncAttributeMaxDynamicSharedMemorySize, smem_mot);

    build_kernel<<<GB, 256>>>(cam, anchors, scales, afeat, tfeat, factors, vis, knn, out, M);
    mlp_wmma_kernel<56,51,16,10,0><<<GP, 256, smem_op >>>(taf,  op_w1,  op_b1,  op_w2,  op_b2,  pf, out, M);
    mlp_wmma_kernel<56,51,32,30,1><<<GP, 256, smem_col>>>(taf,  col_w1, col_b1, col_w2, col_b2, pf, out, M);
    mlp_wmma_kernel<56,51,80,70,2><<<GP, 256, smem_cov>>>(taf,  cov_w1, cov_b1, cov_w2, cov_b2, pf, out, M);
    mlp_wmma_kernel<48,48,48,37,3><<<GP, 256, smem_mot>>>(tafm, mot_w1, mot_b1, mot_w2, mot_b2, mf, out, M);
}

// round 9
// speedup vs baseline: 1.5209x; 1.0055x over previous
#include <cuda_runtime.h>
#include <mma.h>
#include <math.h>

using namespace nvcuda;

#define MAXM 400000

// row-major, pre-rounded-to-tf32 scratch
__device__ __align__(256) float g_taf[(size_t)MAXM * 56 + 1024];   // [M][56], cols 51..55 = 0
__device__ __align__(256) float g_tafm[(size_t)MAXM * 48 + 1024];  // [M][48]
__device__ float g_pf[MAXM + 1024];
__device__ float g_mf[MAXM + 1024];

__device__ __forceinline__ float sigmoidf_(float x) { return 1.f / (1.f + expf(-x)); }
__device__ __forceinline__ float tf32r(float x) { return wmma::__float_to_tf32(x); }

// ================= builder =================
__global__ __launch_bounds__(256)
void build_kernel(const float* __restrict__ cam,
                  const float* __restrict__ anchors,
                  const float* __restrict__ scales,
                  const float* __restrict__ afeat,
                  const float* __restrict__ tfeat,
                  const float* __restrict__ factors,
                  const int* __restrict__ vis,
                  const int* __restrict__ knn,
                  float* __restrict__ out, int M)
{
    int m = blockIdx.x * 256 + threadIdx.x;
    if (m >= M) return;
    int idx = vis[m];

    float a[56];
    const float4* fp = reinterpret_cast<const float4*>(afeat + (long long)idx * 32);
    #pragma unroll
    for (int q = 0; q < 8; q++) {
        float4 v = __ldg(fp + q);
        a[4*q+0] = v.x; a[4*q+1] = v.y; a[4*q+2] = v.z; a[4*q+3] = v.w;
    }
    float ax = __ldg(anchors + (long long)idx * 3 + 0);
    float ay = __ldg(anchors + (long long)idx * 3 + 1);
    float az = __ldg(anchors + (long long)idx * 3 + 2);
    float vx = ax - cam[3], vy = ay - cam[7], vz = az - cam[11];
    float nrm = sqrtf(vx*vx + vy*vy + vz*vz);
    float inv = 1.f / fmaxf(nrm, 1e-8f);
    a[32] = vx * inv; a[33] = vy * inv; a[34] = vz * inv;

    float4 fc = __ldg(reinterpret_cast<const float4*>(factors + (long long)idx * 4));
    float tff = fc.x, mf = fc.y, kf = fc.z, pf = fc.w;

    const float4* tp = reinterpret_cast<const float4*>(tfeat + (long long)idx * 256 + 112);
    #pragma unroll
    for (int q = 0; q < 4; q++) {
        float4 v = __ldg(tp + q);
        a[35+4*q+0] = v.x*tff; a[35+4*q+1] = v.y*tff;
        a[35+4*q+2] = v.z*tff; a[35+4*q+3] = v.w*tff;
    }
    a[51] = 0.f; a[52] = 0.f; a[53] = 0.f; a[54] = 0.f; a[55] = 0.f;

    float4* tr = reinterpret_cast<float4*>(g_taf + (size_t)m * 56);
    #pragma unroll
    for (int q = 0; q < 14; q++)
        tr[q] = make_float4(tf32r(a[4*q]), tf32r(a[4*q+1]), tf32r(a[4*q+2]), tf32r(a[4*q+3]));
    g_pf[m] = pf;
    g_mf[m] = mf;

    // ---- knn mix -> taf_ ----
    float facc[48];
    #pragma unroll
    for (int i = 0; i < 48; i++) facc[i] = 0.f;
    const int* kp = knn + (long long)idx * 6;
    #pragma unroll 1
    for (int nb = 0; nb < 6; nb++) {
        int nidx = __ldg(kp + nb);
        const float4* nf = reinterpret_cast<const float4*>(afeat + (long long)nidx * 32);
        #pragma unroll
        for (int q = 0; q < 8; q++) {
            float4 v = __ldg(nf + q);
            facc[4*q+0] += v.x; facc[4*q+1] += v.y;
            facc[4*q+2] += v.z; facc[4*q+3] += v.w;
        }
        const float4* nt = reinterpret_cast<const float4*>(tfeat + (long long)nidx * 256 + 112);
        #pragma unroll
        for (int q = 0; q < 4; q++) {
            float4 v = __ldg(nt + q);
            facc[32+4*q+0] += v.x; facc[32+4*q+1] += v.y;
            facc[32+4*q+2] += v.z; facc[32+4*q+3] += v.w;
        }
    }
    float wk = (1.f - kf) * (1.f / 6.f);
    float b[48];
    #pragma unroll
    for (int i = 0; i < 32; i++) b[i] = kf * a[i] + wk * facc[i];
    #pragma unroll
    for (int c = 0; c < 16; c++) b[32+c] = kf * a[35+c] + wk * facc[32+c];

    float4* mr = reinterpret_cast<float4*>(g_tafm + (size_t)m * 48);
    #pragma unroll
    for (int q = 0; q < 12; q++)
        mr[q] = make_float4(tf32r(b[4*q]), tf32r(b[4*q+1]), tf32r(b[4*q+2]), tf32r(b[4*q+3]));

    // ---- epilogue columns of out_m (full fp32) ----
    float* om = out + (long long)M * 110 + (long long)m * 50;
    const float* sp = scales + (long long)idx * 6;
    om[37] = expf(__ldg(sp + 0));
    om[38] = expf(__ldg(sp + 1));
    om[39] = expf(__ldg(sp + 2));
    om[40] = expf(__ldg(sp + 3)) * pf;
    om[41] = expf(__ldg(sp + 4)) * pf;
    om[42] = expf(__ldg(sp + 5)) * pf;
    om[43] = tff; om[44] = mf; om[45] = kf; om[46] = pf;
    om[47] = ax; om[48] = ay; om[49] = az;
}

// ================= combined op+col+cov wmma kernel =================
// W1c [56x192] (op|col|cov), W2c [64x128] (op16|col32|cov80).
// Per-warp slab: X [16x60] then H [16x196]. C2: op->X(str16), col->X+256(str32), cov->H(str196).
#define XS 60
#define HS 196
#define W1S 192
#define W2S 128
#define OW1_3 0
#define OW2_3 10752
#define OB1R_3 18944
#define OB2R_3 22016
#define OWRP_3 24064
#define SLAB_3 4096
#define SMEM3_FLOATS (OWRP_3 + 8 * SLAB_3)

__global__ __launch_bounds__(256, 1)
void mlp3_kernel(const float* __restrict__ xin,
                 const float* __restrict__ op_w1,  const float* __restrict__ op_b1,
                 const float* __restrict__ op_w2,  const float* __restrict__ op_b2,
                 const float* __restrict__ col_w1, const float* __restrict__ col_b1,
                 const float* __restrict__ col_w2, const float* __restrict__ col_b2,
                 const float* __restrict__ cov_w1, const float* __restrict__ cov_b1,
                 const float* __restrict__ cov_w2, const float* __restrict__ cov_b2,
                 const float* __restrict__ pfv,
                 float* __restrict__ out, int M)
{
    extern __shared__ float S[];
    const int tid = threadIdx.x;
    const int warp = tid >> 5;
    const int lane = tid & 31;

    // ---- stage combined weights (once per block) ----
    for (int i = tid; i < 56 * W1S; i += 256) {
        int row = i / W1S, c = i - row * W1S;
        int sel = c >> 6, cc = c & 63;
        float v = 0.f;
        if (row < 51)
            v = (sel == 0) ? op_w1[row * 64 + cc]
              : (sel == 1) ? col_w1[row * 64 + cc]
                           : cov_w1[row * 64 + cc];
        S[OW1_3 + i] = tf32r(v);
    }
    for (int i = tid; i < 64 * W2S; i += 256) {
        int j = i >> 7, c = i & 127;
        float v = 0.f;
        if (c < 16)       { if (c < 10)      v = op_w2 [j * 10 + c]; }
        else if (c < 48)  { if (c - 16 < 30) v = col_w2[j * 30 + (c - 16)]; }
        else              { if (c - 48 < 70) v = cov_w2[j * 70 + (c - 48)]; }
        S[OW2_3 + i] = tf32r(v);
    }
    if (tid < W1S) {
        int sel = tid >> 6, cc = tid & 63;
        S[OB1R_3 + tid] = (sel == 0) ? op_b1[cc] : (sel == 1) ? col_b1[cc] : cov_b1[cc];
    }
    if (tid < W2S) {
        float v = 0.f;
        if (tid < 16)      { if (tid < 10)      v = op_b2 [tid]; }
        else if (tid < 48) { if (tid - 16 < 30) v = col_b2[tid - 16]; }
        else               { if (tid - 48 < 70) v = cov_b2[tid - 48]; }
        S[OB2R_3 + tid] = v;
    }
    __syncthreads();
    for (int i = tid; i < 16 * W1S; i += 256)
        if (i >= W1S) S[OB1R_3 + i] = S[OB1R_3 + (i % W1S)];
    for (int i = tid; i < 16 * W2S; i += 256)
        if (i >= W2S) S[OB2R_3 + i] = S[OB2R_3 + (i & 127)];
    __syncthreads();

    float* Xp = S + OWRP_3 + warp * SLAB_3;
    float* Hp = Xp + 16 * XS;
    const int tiles = (M + 15) >> 4;

    for (int t = blockIdx.x * 8 + warp; t < tiles; t += gridDim.x * 8) {
        // ---- stage X tile [16x56] coalesced -> slab stride 60 ----
        {
            const float* src = xin + (size_t)t * 16 * 56;
            #pragma unroll
            for (int it = 0; it < 7; it++) {
                int e = lane * 4 + it * 128;
                float4 v = __ldg(reinterpret_cast<const float4*>(src + e));
                int row = e / 56, c = e - row * 56;
                *reinterpret_cast<float4*>(Xp + row * XS + c) = v;
            }
        }
        __syncwarp();

        // ---- GEMM1: [16x56] @ [56x192], bias preloaded ----
        wmma::fragment<wmma::accumulator, 16, 16, 8, float> c1[12];
        #pragma unroll
        for (int n = 0; n < 12; n++)
            wmma::load_matrix_sync(c1[n], S + OB1R_3 + n * 16, W1S, wmma::mem_row_major);
        #pragma unroll 1
        for (int k = 0; k < 7; k++) {
            wmma::fragment<wmma::matrix_a, 16, 16, 8, wmma::precision::tf32, wmma::row_major> af;
            wmma::load_matrix_sync(af, Xp + k * 8, XS);
            #pragma unroll
            for (int n = 0; n < 12; n++) {
                wmma::fragment<wmma::matrix_b, 16, 16, 8, wmma::precision::tf32, wmma::row_major> bf;
                wmma::load_matrix_sync(bf, S + OW1_3 + k * 8 * W1S + n * 16, W1S);
                wmma::mma_sync(c1[n], af, bf, c1[n]);
            }
        }
        #pragma unroll
        for (int n = 0; n < 12; n++) {
            #pragma unroll
            for (int i = 0; i < c1[n].num_elements; i++)
                c1[n].x[i] = tf32r(fmaxf(c1[n].x[i], 0.f));
            wmma::store_matrix_sync(Hp + n * 16, c1[n], HS, wmma::mem_row_major);
        }
        __syncwarp();

        // ---- GEMM2 op: H[:,0:64] @ W2c[:,0:16] -> Xp (stride 16) ----
        {
            wmma::fragment<wmma::accumulator, 16, 16, 8, float> c2;
            wmma::load_matrix_sync(c2, S + OB2R_3 + 0, W2S, wmma::mem_row_major);
            #pragma unroll 1
            for (int k = 0; k < 8; k++) {
                wmma::fragment<wmma::matrix_a, 16, 16, 8, wmma::precision::tf32, wmma::row_major> af;
                wmma::load_matrix_sync(af, Hp + k * 8, HS);
                wmma::fragment<wmma::matrix_b, 16, 16, 8, wmma::precision::tf32, wmma::row_major> bf;
                wmma::load_matrix_sync(bf, S + OW2_3 + k * 8 * W2S + 0, W2S);
                wmma::mma_sync(c2, af, bf, c2);
            }
            wmma::store_matrix_sync(Xp, c2, 16, wmma::mem_row_major);
        }
        // ---- GEMM2 col: H[:,64:128] @ W2c[:,16:48] -> Xp+256 (stride 32) ----
        {
            wmma::fragment<wmma::accumulator, 16, 16, 8, float> c2[2];
            #pragma unroll
            for (int n = 0; n < 2; n++)
                wmma::load_matrix_sync(c2[n], S + OB2R_3 + 16 + n * 16, W2S, wmma::mem_row_major);
            #pragma unroll 1
            for (int k = 0; k < 8; k++) {
                wmma::fragment<wmma::matrix_a, 16, 16, 8, wmma::precision::tf32, wmma::row_major> af;
                wmma::load_matrix_sync(af, Hp + 64 + k * 8, HS);
                #pragma unroll
                for (int n = 0; n < 2; n++) {
                    wmma::fragment<wmma::matrix_b, 16, 16, 8, wmma::precision::tf32, wmma::row_major> bf;
                    wmma::load_matrix_sync(bf, S + OW2_3 + k * 8 * W2S + 16 + n * 16, W2S);
                    wmma::mma_sync(c2[n], af, bf, c2[n]);
                }
            }
            #pragma unroll
            for (int n = 0; n < 2; n++)
                wmma::store_matrix_sync(Xp + 256 + n * 16, c2[n], 32, wmma::mem_row_major);
        }
        // ---- GEMM2 cov: H[:,128:192] @ W2c[:,48:128] -> Hp (stride 196, cols 0..79) ----
        {
            wmma::fragment<wmma::accumulator, 16, 16, 8, float> c2[5];
            #pragma unroll
            for (int n = 0; n < 5; n++)
                wmma::load_matrix_sync(c2[n], S + OB2R_3 + 48 + n * 16, W2S, wmma::mem_row_major);
            #pragma unroll 1
            for (int k = 0; k < 8; k++) {
                wmma::fragment<wmma::matrix_a, 16, 16, 8, wmma::precision::tf32, wmma::row_major> af;
                wmma::load_matrix_sync(af, Hp + 128 + k * 8, HS);
                #pragma unroll
                for (int n = 0; n < 5; n++) {
                    wmma::fragment<wmma::matrix_b, 16, 16, 8, wmma::precision::tf32, wmma::row_major> bf;
                    wmma::load_matrix_sync(bf, S + OW2_3 + k * 8 * W2S + 48 + n * 16, W2S);
                    wmma::mma_sync(c2[n], af, bf, c2[n]);
                }
            }
            #pragma unroll
            for (int n = 0; n < 5; n++)
                wmma::store_matrix_sync(Hp + n * 16, c2[n], HS, wmma::mem_row_major);
        }
        __syncwarp();

        // ---- epilogue: 2 lanes per point, 55 outputs each ----
        {
            int p = lane >> 1, half = lane & 1;
            size_t m = (size_t)t * 16 + p;
            if (m < (size_t)M) {
                float pf = __ldg(pfv + m);
                float* omk = out + m * 110;
                const float* oc = Xp + p * 16;
                const float* cc = Xp + 256 + p * 32;
                const float* vc = Hp + p * HS;
                #pragma unroll
                for (int k = half * 5; k < half * 5 + 5; k++)
                    omk[k * 11] = tanhf(oc[k]) * pf;
                #pragma unroll
                for (int k = half * 15; k < half * 15 + 15; k++) {
                    int kd = k / 3;
                    omk[kd * 11 + 1 + (k - kd * 3)] = sigmoidf_(cc[k]);
                }
                #pragma unroll
                for (int k = half * 35; k < half * 35 + 35; k++) {
                    int kd = k / 7;
                    omk[kd * 11 + 4 + (k - kd * 7)] = vc[k];
                }
            }
        }
        __syncwarp();
    }
}

// ================= motion wmma kernel (X staged) =================
// slab: X [16x52] then H [16x68]; C2 -> X (stride 52)
#define MXS 52
#define MHS 68
#define OW1_M 0
#define OW2_M 3072
#define OB1R_M 6144
#define OB2R_M 7168
#define OWRP_M 7936
#define SLAB_M 1920
#define SMEMM_FLOATS (OWRP_M + 8 * SLAB_M)

__global__ __launch_bounds__(256, 2)
void mlp_mot_kernel(const float* __restrict__ xin,
                    const float* __restrict__ w1g, const float* __restrict__ b1g,
                    const float* __restrict__ w2g, const float* __restrict__ b2g,
                    const float* __restrict__ mfv,
                    float* __restrict__ out, int M)
{
    extern __shared__ float S[];
    const int tid = threadIdx.x;
    const int warp = tid >> 5;
    const int lane = tid & 31;

    for (int i = tid; i < 48 * 64; i += 256) S[OW1_M + i] = tf32r(w1g[i]);
    for (int i = tid; i < 64 * 48; i += 256) {
        int j = i / 48, k = i - j * 48;
        S[OW2_M + i] = (k < 37) ? tf32r(w2g[j * 37 + k]) : 0.f;
    }
    if (tid < 64) {
        float acc = b1g[tid];
        #pragma unroll
        for (int t = 0; t < 8; t++) {
            float ang = exp2f((float)t) * 1.5707963267948966f;
            acc = fmaf(sinf(ang), w1g[(48 + t) * 64 + tid], acc);
            acc = fmaf(cosf(ang), w1g[(56 + t) * 64 + tid], acc);
        }
        S[OB1R_M + tid] = acc;
    }
    if (tid < 48) S[OB2R_M + tid] = (tid < 37) ? b2g[tid] : 0.f;
    __syncthreads();
    for (int i = tid; i < 16 * 64; i += 256)
        if (i >= 64) S[OB1R_M + i] = S[OB1R_M + (i & 63)];
    for (int i = tid; i < 16 * 48; i += 256)
        if (i >= 48) S[OB2R_M + i] = S[OB2R_M + (i % 48)];
    __syncthreads();

    float* Xp = S + OWRP_M + warp * SLAB_M;
    float* Hp = Xp + 16 * MXS;
    const int tiles = (M + 15) >> 4;

    for (int t = blockIdx.x * 8 + warp; t < tiles; t += gridDim.x * 8) {
        // stage X [16x48] -> stride 52 (768 floats = 6 float4/lane)
        {
            const float* src = xin + (size_t)t * 16 * 48;
            #pragma unroll
            for (int it = 0; it < 6; it++) {
                int e = lane * 4 + it * 128;
                float4 v = __ldg(reinterpret_cast<const float4*>(src + e));
                int row = e / 48, c = e - row * 48;
                *reinterpret_cast<float4*>(Xp + row * MXS + c) = v;
            }
        }
        __syncwarp();

        wmma::fragment<wmma::accumulator, 16, 16, 8, float> c1[4];
        #pragma unroll
        for (int n = 0; n < 4; n++)
            wmma::load_matrix_sync(c1[n], S + OB1R_M + n * 16, 64, wmma::mem_row_major);
        #pragma unroll 1
        for (int k = 0; k < 6; k++) {
            wmma::fragment<wmma::matrix_a, 16, 16, 8, wmma::precision::tf32, wmma::row_major> af;
            wmma::load_matrix_sync(af, Xp + k * 8, MXS);
            #pragma unroll
            for (int n = 0; n < 4; n++) {
                wmma::fragment<wmma::matrix_b, 16, 16, 8, wmma::precision::tf32, wmma::row_major> bf;
                wmma::load_matrix_sync(bf, S + OW1_M + k * 8 * 64 + n * 16, 64);
                wmma::mma_sync(c1[n], af, bf, c1[n]);
            }
        }
        #pragma unroll
        for (int n = 0; n < 4; n++) {
            #pragma unroll
            for (int i = 0; i < c1[n].num_elements; i++)
                c1[n].x[i] = tf32r(fmaxf(c1[n].x[i], 0.f));
            wmma::store_matrix_sync(Hp + n * 16, c1[n], MHS, wmma::mem_row_major);
        }
        __syncwarp();

        wmma::fragment<wmma::accumulator, 16, 16, 8, float> c2[3];
        #pragma unroll
        for (int n = 0; n < 3; n++)
            wmma::load_matrix_sync(c2[n], S + OB2R_M + n * 16, 48, wmma::mem_row_major);
        #pragma unroll 1
        for (int k = 0; k < 8; k++) {
            wmma::fragment<wmma::matrix_a, 16, 16, 8, wmma::precision::tf32, wmma::row_major> af;
            wmma::load_matrix_sync(af, Hp + k * 8, MHS);
            #pragma unroll
            for (int n = 0; n < 3; n++) {
                wmma::fragment<wmma::matrix_b, 16, 16, 8, wmma::precision::tf32, wmma::row_major> bf;
                wmma::load_matrix_sync(bf, S + OW2_M + k * 8 * 48 + n * 16, 48);
                wmma::mma_sync(c2[n], af, bf, c2[n]);
            }
        }
        __syncwarp();
        #pragma unroll
        for (int n = 0; n < 3; n++)
            wmma::store_matrix_sync(Xp + n * 16, c2[n], MXS, wmma::mem_row_major);
        __syncwarp();

        {
            int p = lane >> 1, half = lane & 1;
            size_t m = (size_t)t * 16 + p;
            if (m < (size_t)M) {
                float mfs = __ldg(mfv + m);
                float* om = out + (size_t)M * 110 + m * 50;
                const float* c2r = Xp + p * MXS;
                int k0 = half ? 19 : 0, k1 = half ? 37 : 19;
                for (int k = k0; k < k1; k++)
                    om[k] = c2r[k] * mfs;
            }
        }
        __syncwarp();
    }
}

// ================= launch =================
extern "C" void kernel_launch(void* const* d_in, const int* in_sizes, int n_in,
                              void* d_out, int out_size)
{
    const float* cam     = (const float*)d_in[0];
    const float* anchors = (const float*)d_in[1];
    const float* scales  = (const float*)d_in[2];
    const float* afeat   = (const float*)d_in[3];
    const float* tfeat   = (const float*)d_in[4];
    const float* factors = (const float*)d_in[5];
    const float* op_w1   = (const float*)d_in[6];
    const float* op_b1   = (const float*)d_in[7];
    const float* op_w2   = (const float*)d_in[8];
    const float* op_b2   = (const float*)d_in[9];
    const float* col_w1  = (const float*)d_in[10];
    const float* col_b1  = (const float*)d_in[11];
    const float* col_w2  = (const float*)d_in[12];
    const float* col_b2  = (const float*)d_in[13];
    const float* cov_w1  = (const float*)d_in[14];
    const float* cov_b1  = (const float*)d_in[15];
    const float* cov_w2  = (const float*)d_in[16];
    const float* cov_b2  = (const float*)d_in[17];
    const float* mot_w1  = (const float*)d_in[18];
    const float* mot_b1  = (const float*)d_in[19];
    const float* mot_w2  = (const float*)d_in[20];
    const float* mot_b2  = (const float*)d_in[21];
    const int*   vis     = (const int*)d_in[22];
    const int*   knn     = (const int*)d_in[23];

    int M = in_sizes[22];
    float* out = (float*)d_out;

    float *taf, *tafm, *pf, *mf;
    cudaGetSymbolAddress((void**)&taf,  g_taf);
    cudaGetSymbolAddress((void**)&tafm, g_tafm);
    cudaGetSymbolAddress((void**)&pf,   g_pf);
    cudaGetSymbolAddress((void**)&mf,   g_mf);

    const int GB = (M + 255) / 256;

    const int SMEM3 = SMEM3_FLOATS * 4;   // 227,328 B
    const int SMEMM = SMEMM_FLOATS * 4;   // 93,184 B
    cudaFuncSetAttribute(mlp3_kernel,    cudaFuncAttributeMaxDynamicSharedMemorySize, SMEM3);
    cudaFuncSetAttribute(mlp_mot_kernel, cudaFuncAttributeMaxDynamicSharedMemorySize, SMEMM);

    build_kernel<<<GB, 256>>>(cam, anchors, scales, afeat, tfeat, factors, vis, knn, out, M);
    mlp3_kernel<<<148, 256, SMEM3>>>(
        taf,
        op_w1, op_b1, op_w2, op_b2,
        col_w1, col_b1, col_w2, col_b2,
        cov_w1, cov_b1, cov_w2, cov_b2,
        pf, out, M);
    mlp_mot_kernel<<<296, 256, SMEMM>>>(tafm, mot_w1, mot_b1, mot_w2, mot_b2, mf, out, M);
}

// round 10
// speedup vs baseline: 1.6399x; 1.0782x over previous
#include <cuda_runtime.h>
#include <mma.h>
#include <math.h>

using namespace nvcuda;

#define MAXM 400000

__device__ __align__(256) float g_taf[(size_t)MAXM * 56 + 1024];   // [M][56] tf32, cols 51..55 = 0
__device__ __align__(256) float g_tafm[(size_t)MAXM * 48 + 1024];  // [M][48] tf32
__device__ float g_pf[MAXM + 1024];
__device__ float g_mf[MAXM + 1024];

__device__ __forceinline__ float sigmoidf_(float x) { return 1.f / (1.f + expf(-x)); }
__device__ __forceinline__ float tf32r(float x) { return wmma::__float_to_tf32(x); }

// ================= builder: KNN-first ordering, unrolled gathers =================
__global__ __launch_bounds__(256)
void build_kernel(const float* __restrict__ cam,
                  const float* __restrict__ anchors,
                  const float* __restrict__ scales,
                  const float* __restrict__ afeat,
                  const float* __restrict__ tfeat,
                  const float* __restrict__ factors,
                  const int* __restrict__ vis,
                  const int* __restrict__ knn,
                  float* __restrict__ out, int M)
{
    int m = blockIdx.x * 256 + threadIdx.x;
    if (m >= M) return;
    int idx = vis[m];

    // ---- phase 1: KNN gather (only facc live; high MLP) ----
    const int* kp = knn + (long long)idx * 6;
    int n0 = __ldg(kp + 0), n1 = __ldg(kp + 1), n2 = __ldg(kp + 2);
    int n3 = __ldg(kp + 3), n4 = __ldg(kp + 4), n5 = __ldg(kp + 5);
    int nid[6] = { n0, n1, n2, n3, n4, n5 };

    float facc[48];
    #pragma unroll
    for (int i = 0; i < 48; i++) facc[i] = 0.f;

    #pragma unroll
    for (int nb = 0; nb < 6; nb += 2) {
        int ia = nid[nb], ib = nid[nb + 1];
        const float4* fa = reinterpret_cast<const float4*>(afeat + (long long)ia * 32);
        const float4* fb = reinterpret_cast<const float4*>(afeat + (long long)ib * 32);
        float4 va[8], vb[8];
        #pragma unroll
        for (int q = 0; q < 8; q++) { va[q] = __ldg(fa + q); vb[q] = __ldg(fb + q); }
        #pragma unroll
        for (int q = 0; q < 8; q++) {
            facc[4*q+0] += va[q].x + vb[q].x;
            facc[4*q+1] += va[q].y + vb[q].y;
            facc[4*q+2] += va[q].z + vb[q].z;
            facc[4*q+3] += va[q].w + vb[q].w;
        }
        const float4* ta = reinterpret_cast<const float4*>(tfeat + (long long)ia * 256 + 112);
        const float4* tb = reinterpret_cast<const float4*>(tfeat + (long long)ib * 256 + 112);
        float4 wa[4], wb[4];
        #pragma unroll
        for (int q = 0; q < 4; q++) { wa[q] = __ldg(ta + q); wb[q] = __ldg(tb + q); }
        #pragma unroll
        for (int q = 0; q < 4; q++) {
            facc[32+4*q+0] += wa[q].x + wb[q].x;
            facc[32+4*q+1] += wa[q].y + wb[q].y;
            facc[32+4*q+2] += wa[q].z + wb[q].z;
            facc[32+4*q+3] += wa[q].w + wb[q].w;
        }
    }

    // ---- phase 2: own-point gather ----
    float a[51];
    const float4* fp = reinterpret_cast<const float4*>(afeat + (long long)idx * 32);
    #pragma unroll
    for (int q = 0; q < 8; q++) {
        float4 v = __ldg(fp + q);
        a[4*q+0] = v.x; a[4*q+1] = v.y; a[4*q+2] = v.z; a[4*q+3] = v.w;
    }
    float ax = __ldg(anchors + (long long)idx * 3 + 0);
    float ay = __ldg(anchors + (long long)idx * 3 + 1);
    float az = __ldg(anchors + (long long)idx * 3 + 2);
    float vx = ax - cam[3], vy = ay - cam[7], vz = az - cam[11];
    float nrm = sqrtf(vx*vx + vy*vy + vz*vz);
    float inv = 1.f / fmaxf(nrm, 1e-8f);
    a[32] = vx * inv; a[33] = vy * inv; a[34] = vz * inv;

    float4 fc = __ldg(reinterpret_cast<const float4*>(factors + (long long)idx * 4));
    float tff = fc.x, mf = fc.y, kf = fc.z, pf = fc.w;

    const float4* tp = reinterpret_cast<const float4*>(tfeat + (long long)idx * 256 + 112);
    #pragma unroll
    for (int q = 0; q < 4; q++) {
        float4 v = __ldg(tp + q);
        a[35+4*q+0] = v.x*tff; a[35+4*q+1] = v.y*tff;
        a[35+4*q+2] = v.z*tff; a[35+4*q+3] = v.w*tff;
    }

    // ---- write taf (tf32-rounded), pf/mf ----
    {
        float4* tr = reinterpret_cast<float4*>(g_taf + (size_t)m * 56);
        #pragma unroll
        for (int q = 0; q < 12; q++)
            tr[q] = make_float4(tf32r(a[4*q]), tf32r(a[4*q+1]), tf32r(a[4*q+2]), tf32r(a[4*q+3]));
        tr[12] = make_float4(tf32r(a[48]), tf32r(a[49]), tf32r(a[50]), 0.f);
        tr[13] = make_float4(0.f, 0.f, 0.f, 0.f);
    }
    g_pf[m] = pf;
    g_mf[m] = mf;

    // ---- mix -> tafm (tf32-rounded) ----
    {
        float wk = (1.f - kf) * (1.f / 6.f);
        float b[48];
        #pragma unroll
        for (int i = 0; i < 32; i++) b[i] = kf * a[i] + wk * facc[i];
        #pragma unroll
        for (int c = 0; c < 16; c++) b[32+c] = kf * a[35+c] + wk * facc[32+c];
        float4* mr = reinterpret_cast<float4*>(g_tafm + (size_t)m * 48);
        #pragma unroll
        for (int q = 0; q < 12; q++)
            mr[q] = make_float4(tf32r(b[4*q]), tf32r(b[4*q+1]), tf32r(b[4*q+2]), tf32r(b[4*q+3]));
    }

    // ---- epilogue columns of out_m (fp32) ----
    float* om = out + (long long)M * 110 + (long long)m * 50;
    const float* sp = scales + (long long)idx * 6;
    om[37] = expf(__ldg(sp + 0));
    om[38] = expf(__ldg(sp + 1));
    om[39] = expf(__ldg(sp + 2));
    om[40] = expf(__ldg(sp + 3)) * pf;
    om[41] = expf(__ldg(sp + 4)) * pf;
    om[42] = expf(__ldg(sp + 5)) * pf;
    om[43] = tff; om[44] = mf; om[45] = kf; om[46] = pf;
    om[47] = ax; om[48] = ay; om[49] = az;
}

// ================= fused op+col+cov wmma kernel, per-slice, 14 warps =================
// W1c [56x192] (op|col|cov), W2c [64x128] (op@0 w16 | col@16 w32 | cov@48 w80)
// per-warp slab: X [16x60] + H/C2 [16x84]
#define W1S 192
#define W2S 128
#define XS3 60
#define HS3 84
#define OW1_3 0
#define OW2_3 10752
#define OB1R_3 18944          // 16 x 192 replicated b1
#define OB2_3  22016          // 128 raw b2 (epilogue)
#define OWRP_3 22144
#define SLAB_3 2304           // 16*60 + 16*84
#define NW3 14
#define SMEM3_FLOATS (OWRP_3 + NW3 * SLAB_3)

__global__ __launch_bounds__(448, 1)
void mlp3_kernel(const float* __restrict__ xin,
                 const float* __restrict__ op_w1,  const float* __restrict__ op_b1,
                 const float* __restrict__ op_w2,  const float* __restrict__ op_b2,
                 const float* __restrict__ col_w1, const float* __restrict__ col_b1,
                 const float* __restrict__ col_w2, const float* __restrict__ col_b2,
                 const float* __restrict__ cov_w1, const float* __restrict__ cov_b1,
                 const float* __restrict__ cov_w2, const float* __restrict__ cov_b2,
                 const float* __restrict__ pfv,
                 float* __restrict__ out, int M)
{
    extern __shared__ float S[];
    const int tid = threadIdx.x;
    const int warp = tid >> 5;
    const int lane = tid & 31;

    // ---- stage combined weights ----
    for (int i = tid; i < 56 * W1S; i += 448) {
        int row = i / W1S, c = i - row * W1S;
        int sel = c >> 6, cc = c & 63;
        float v = 0.f;
        if (row < 51)
            v = (sel == 0) ? op_w1[row * 64 + cc]
              : (sel == 1) ? col_w1[row * 64 + cc]
                           : cov_w1[row * 64 + cc];
        S[OW1_3 + i] = tf32r(v);
    }
    for (int i = tid; i < 64 * W2S; i += 448) {
        int j = i >> 7, c = i & 127;
        float v = 0.f;
        if (c < 16)       { if (c < 10)      v = op_w2 [j * 10 + c]; }
        else if (c < 48)  { if (c - 16 < 30) v = col_w2[j * 30 + (c - 16)]; }
        else              { if (c - 48 < 70) v = cov_w2[j * 70 + (c - 48)]; }
        S[OW2_3 + i] = tf32r(v);
    }
    if (tid < W1S) {
        int sel = tid >> 6, cc = tid & 63;
        S[OB1R_3 + tid] = (sel == 0) ? op_b1[cc] : (sel == 1) ? col_b1[cc] : cov_b1[cc];
    }
    if (tid < W2S) {
        float v = 0.f;
        if (tid < 16)      { if (tid < 10)      v = op_b2 [tid]; }
        else if (tid < 48) { if (tid - 16 < 30) v = col_b2[tid - 16]; }
        else               { if (tid - 48 < 70) v = cov_b2[tid - 48]; }
        S[OB2_3 + tid] = v;
    }
    __syncthreads();
    for (int i = tid; i < 16 * W1S; i += 448)
        if (i >= W1S) S[OB1R_3 + i] = S[OB1R_3 + (i % W1S)];
    __syncthreads();

    float* Xp = S + OWRP_3 + warp * SLAB_3;
    float* Hp = Xp + 16 * XS3;
    const int tiles = (M + 15) >> 4;

    for (int t = blockIdx.x * NW3 + warp; t < tiles; t += gridDim.x * NW3) {
        // ---- stage X tile [16x56] coalesced -> stride 60 ----
        {
            const float* src = xin + (size_t)t * 16 * 56;
            #pragma unroll
            for (int it = 0; it < 7; it++) {
                int e = lane * 4 + it * 128;
                float4 v = __ldg(reinterpret_cast<const float4*>(src + e));
                int row = e / 56, c = e - row * 56;
                *reinterpret_cast<float4*>(Xp + row * XS3 + c) = v;
            }
        }
        __syncwarp();

        int p = lane >> 1, half = lane & 1;
        size_t m = (size_t)t * 16 + p;
        bool valid = (m < (size_t)M);
        float pf = valid ? __ldg(pfv + m) : 0.f;
        float* omk = out + m * 110;

        // ================ slice loop: 0=op(4x16 H, N2=16) 1=col(N2=32) 2=cov(N2=80) ================
        #pragma unroll 1
        for (int s = 0; s < 3; s++) {
            // ---- GEMM1 slice: [16x56]@[56x64] + b1 ----
            wmma::fragment<wmma::accumulator, 16, 16, 8, float> c1[4];
            #pragma unroll
            for (int n = 0; n < 4; n++)
                wmma::load_matrix_sync(c1[n], S + OB1R_3 + s * 64 + n * 16, W1S, wmma::mem_row_major);
            #pragma unroll 1
            for (int k = 0; k < 7; k++) {
                wmma::fragment<wmma::matrix_a, 16, 16, 8, wmma::precision::tf32, wmma::row_major> af;
                wmma::load_matrix_sync(af, Xp + k * 8, XS3);
                #pragma unroll
                for (int n = 0; n < 4; n++) {
                    wmma::fragment<wmma::matrix_b, 16, 16, 8, wmma::precision::tf32, wmma::row_major> bf;
                    wmma::load_matrix_sync(bf, S + OW1_3 + (k * 8) * W1S + s * 64 + n * 16, W1S);
                    wmma::mma_sync(c1[n], af, bf, c1[n]);
                }
            }
            #pragma unroll
            for (int n = 0; n < 4; n++) {
                #pragma unroll
                for (int i = 0; i < c1[n].num_elements; i++)
                    c1[n].x[i] = tf32r(fmaxf(c1[n].x[i], 0.f));
                wmma::store_matrix_sync(Hp + n * 16, c1[n], HS3, wmma::mem_row_major);
            }
            __syncwarp();

            // ---- GEMM2 slice: [16x64]@[64xN2] ----
            if (s == 0) {
                wmma::fragment<wmma::accumulator, 16, 16, 8, float> c2;
                wmma::fill_fragment(c2, 0.f);
                #pragma unroll 1
                for (int k = 0; k < 8; k++) {
                    wmma::fragment<wmma::matrix_a, 16, 16, 8, wmma::precision::tf32, wmma::row_major> af;
                    wmma::load_matrix_sync(af, Hp + k * 8, HS3);
                    wmma::fragment<wmma::matrix_b, 16, 16, 8, wmma::precision::tf32, wmma::row_major> bf;
                    wmma::load_matrix_sync(bf, S + OW2_3 + (k * 8) * W2S + 0, W2S);
                    wmma::mma_sync(c2, af, bf, c2);
                }
                __syncwarp();
                wmma::store_matrix_sync(Hp, c2, HS3, wmma::mem_row_major);
                __syncwarp();
                if (valid) {
                    const float* cr = Hp + p * HS3;
                    #pragma unroll
                    for (int k = half * 5; k < half * 5 + 5; k++)
                        omk[k * 11] = tanhf(cr[k] + S[OB2_3 + k]) * pf;
                }
            } else if (s == 1) {
                wmma::fragment<wmma::accumulator, 16, 16, 8, float> c2[2];
                #pragma unroll
                for (int n = 0; n < 2; n++) wmma::fill_fragment(c2[n], 0.f);
                #pragma unroll 1
                for (int k = 0; k < 8; k++) {
                    wmma::fragment<wmma::matrix_a, 16, 16, 8, wmma::precision::tf32, wmma::row_major> af;
                    wmma::load_matrix_sync(af, Hp + k * 8, HS3);
                    #pragma unroll
                    for (int n = 0; n < 2; n++) {
                        wmma::fragment<wmma::matrix_b, 16, 16, 8, wmma::precision::tf32, wmma::row_major> bf;
                        wmma::load_matrix_sync(bf, S + OW2_3 + (k * 8) * W2S + 16 + n * 16, W2S);
                        wmma::mma_sync(c2[n], af, bf, c2[n]);
                    }
                }
                __syncwarp();
                #pragma unroll
                for (int n = 0; n < 2; n++)
                    wmma::store_matrix_sync(Hp + n * 16, c2[n], HS3, wmma::mem_row_major);
                __syncwarp();
                if (valid) {
                    const float* cr = Hp + p * HS3;
                    #pragma unroll
                    for (int k = half * 15; k < half * 15 + 15; k++) {
                        int kd = k / 3;
                        omk[kd * 11 + 1 + (k - kd * 3)] = sigmoidf_(cr[k] + S[OB2_3 + 16 + k]);
                    }
                }
            } else {
                wmma::fragment<wmma::accumulator, 16, 16, 8, float> c2[5];
                #pragma unroll
                for (int n = 0; n < 5; n++) wmma::fill_fragment(c2[n], 0.f);
                #pragma unroll 1
                for (int k = 0; k < 8; k++) {
                    wmma::fragment<wmma::matrix_a, 16, 16, 8, wmma::precision::tf32, wmma::row_major> af;
                    wmma::load_matrix_sync(af, Hp + k * 8, HS3);
                    #pragma unroll
                    for (int n = 0; n < 5; n++) {
                        wmma::fragment<wmma::matrix_b, 16, 16, 8, wmma::precision::tf32, wmma::row_major> bf;
                        wmma::load_matrix_sync(bf, S + OW2_3 + (k * 8) * W2S + 48 + n * 16, W2S);
                        wmma::mma_sync(c2[n], af, bf, c2[n]);
                    }
                }
                __syncwarp();
                #pragma unroll
                for (int n = 0; n < 5; n++)
                    wmma::store_matrix_sync(Hp + n * 16, c2[n], HS3, wmma::mem_row_major);
                __syncwarp();
                if (valid) {
                    const float* cr = Hp + p * HS3;
                    #pragma unroll
                    for (int k = half * 35; k < half * 35 + 35; k++) {
                        int kd = k / 7;
                        omk[kd * 11 + 4 + (k - kd * 7)] = cr[k] + S[OB2_3 + 48 + k];
                    }
                }
            }
            __syncwarp();   // scatter reads done before next slice overwrites Hp
        }
    }
}

// ================= motion wmma kernel (unchanged from R9) =================
#define MXS 52
#define MHS 68
#define OW1_M 0
#define OW2_M 3072
#define OB1R_M 6144
#define OB2R_M 7168
#define OWRP_M 7936
#define SLAB_M 1920
#define SMEMM_FLOATS (OWRP_M + 8 * SLAB_M)

__global__ __launch_bounds__(256, 2)
void mlp_mot_kernel(const float* __restrict__ xin,
                    const float* __restrict__ w1g, const float* __restrict__ b1g,
                    const float* __restrict__ w2g, const float* __restrict__ b2g,
                    const float* __restrict__ mfv,
                    float* __restrict__ out, int M)
{
    extern __shared__ float S[];
    const int tid = threadIdx.x;
    const int warp = tid >> 5;
    const int lane = tid & 31;

    for (int i = tid; i < 48 * 64; i += 256) S[OW1_M + i] = tf32r(w1g[i]);
    for (int i = tid; i < 64 * 48; i += 256) {
        int j = i / 48, k = i - j * 48;
        S[OW2_M + i] = (k < 37) ? tf32r(w2g[j * 37 + k]) : 0.f;
    }
    if (tid < 64) {
        float acc = b1g[tid];
        #pragma unroll
        for (int t = 0; t < 8; t++) {
            float ang = exp2f((float)t) * 1.5707963267948966f;
            acc = fmaf(sinf(ang), w1g[(48 + t) * 64 + tid], acc);
            acc = fmaf(cosf(ang), w1g[(56 + t) * 64 + tid], acc);
        }
        S[OB1R_M + tid] = acc;
    }
    if (tid < 48) S[OB2R_M + tid] = (tid < 37) ? b2g[tid] : 0.f;
    __syncthreads();
    for (int i = tid; i < 16 * 64; i += 256)
        if (i >= 64) S[OB1R_M + i] = S[OB1R_M + (i & 63)];
    for (int i = tid; i < 16 * 48; i += 256)
        if (i >= 48) S[OB2R_M + i] = S[OB2R_M + (i % 48)];
    __syncthreads();

    float* Xp = S + OWRP_M + warp * SLAB_M;
    float* Hp = Xp + 16 * MXS;
    const int tiles = (M + 15) >> 4;

    for (int t = blockIdx.x * 8 + warp; t < tiles; t += gridDim.x * 8) {
        {
            const float* src = xin + (size_t)t * 16 * 48;
            #pragma unroll
            for (int it = 0; it < 6; it++) {
                int e = lane * 4 + it * 128;
                float4 v = __ldg(reinterpret_cast<const float4*>(src + e));
                int row = e / 48, c = e - row * 48;
                *reinterpret_cast<float4*>(Xp + row * MXS + c) = v;
            }
        }
        __syncwarp();

        wmma::fragment<wmma::accumulator, 16, 16, 8, float> c1[4];
        #pragma unroll
        for (int n = 0; n < 4; n++)
            wmma::load_matrix_sync(c1[n], S + OB1R_M + n * 16, 64, wmma::mem_row_major);
        #pragma unroll 1
        for (int k = 0; k < 6; k++) {
            wmma::fragment<wmma::matrix_a, 16, 16, 8, wmma::precision::tf32, wmma::row_major> af;
            wmma::load_matrix_sync(af, Xp + k * 8, MXS);
            #pragma unroll
            for (int n = 0; n < 4; n++) {
                wmma::fragment<wmma::matrix_b, 16, 16, 8, wmma::precision::tf32, wmma::row_major> bf;
                wmma::load_matrix_sync(bf, S + OW1_M + k * 8 * 64 + n * 16, 64);
                wmma::mma_sync(c1[n], af, bf, c1[n]);
            }
        }
        #pragma unroll
        for (int n = 0; n < 4; n++) {
            #pragma unroll
            for (int i = 0; i < c1[n].num_elements; i++)
                c1[n].x[i] = tf32r(fmaxf(c1[n].x[i], 0.f));
            wmma::store_matrix_sync(Hp + n * 16, c1[n], MHS, wmma::mem_row_major);
        }
        __syncwarp();

        wmma::fragment<wmma::accumulator, 16, 16, 8, float> c2[3];
        #pragma unroll
        for (int n = 0; n < 3; n++)
            wmma::load_matrix_sync(c2[n], S + OB2R_M + n * 16, 48, wmma::mem_row_major);
        #pragma unroll 1
        for (int k = 0; k < 8; k++) {
            wmma::fragment<wmma::matrix_a, 16, 16, 8, wmma::precision::tf32, wmma::row_major> af;
            wmma::load_matrix_sync(af, Hp + k * 8, MHS);
            #pragma unroll
            for (int n = 0; n < 3; n++) {
                wmma::fragment<wmma::matrix_b, 16, 16, 8, wmma::precision::tf32, wmma::row_major> bf;
                wmma::load_matrix_sync(bf, S + OW2_M + k * 8 * 48 + n * 16, 48);
                wmma::mma_sync(c2[n], af, bf, c2[n]);
            }
        }
        __syncwarp();
        #pragma unroll
        for (int n = 0; n < 3; n++)
            wmma::store_matrix_sync(Xp + n * 16, c2[n], MXS, wmma::mem_row_major);
        __syncwarp();

        {
            int p = lane >> 1, half = lane & 1;
            size_t m = (size_t)t * 16 + p;
            if (m < (size_t)M) {
                float mfs = __ldg(mfv + m);
                float* om = out + (size_t)M * 110 + m * 50;
                const float* c2r = Xp + p * MXS;
                int k0 = half ? 19 : 0, k1 = half ? 37 : 19;
                for (int k = k0; k < k1; k++)
                    om[k] = c2r[k] * mfs;
            }
        }
        __syncwarp();
    }
}

// ================= launch =================
extern "C" void kernel_launch(void* const* d_in, const int* in_sizes, int n_in,
                              void* d_out, int out_size)
{
    const float* cam     = (const float*)d_in[0];
    const float* anchors = (const float*)d_in[1];
    const float* scales  = (const float*)d_in[2];
    const float* afeat   = (const float*)d_in[3];
    const float* tfeat   = (const float*)d_in[4];
    const float* factors = (const float*)d_in[5];
    const float* op_w1   = (const float*)d_in[6];
    const float* op_b1   = (const float*)d_in[7];
    const float* op_w2   = (const float*)d_in[8];
    const float* op_b2   = (const float*)d_in[9];
    const float* col_w1  = (const float*)d_in[10];
    const float* col_b1  = (const float*)d_in[11];
    const float* col_w2  = (const float*)d_in[12];
    const float* col_b2  = (const float*)d_in[13];
    const float* cov_w1  = (const float*)d_in[14];
    const float* cov_b1  = (const float*)d_in[15];
    const float* cov_w2  = (const float*)d_in[16];
    const float* cov_b2  = (const float*)d_in[17];
    const float* mot_w1  = (const float*)d_in[18];
    const float* mot_b1  = (const float*)d_in[19];
    const float* mot_w2  = (const float*)d_in[20];
    const float* mot_b2  = (const float*)d_in[21];
    const int*   vis     = (const int*)d_in[22];
    const int*   knn     = (const int*)d_in[23];

    int M = in_sizes[22];
    float* out = (float*)d_out;

    float *taf, *tafm, *pf, *mf;
    cudaGetSymbolAddress((void**)&taf,  g_taf);
    cudaGetSymbolAddress((void**)&tafm, g_tafm);
    cudaGetSymbolAddress((void**)&pf,   g_pf);
    cudaGetSymbolAddress((void**)&mf,   g_mf);

    const int GB = (M + 255) / 256;

    const int SMEM3 = SMEM3_FLOATS * 4;   // ~217.6 KB
    const int SMEMM = SMEMM_FLOATS * 4;   // ~93 KB
    cudaFuncSetAttribute(mlp3_kernel,    cudaFuncAttributeMaxDynamicSharedMemorySize, SMEM3);
    cudaFuncSetAttribute(mlp_mot_kernel, cudaFuncAttributeMaxDynamicSharedMemorySize, SMEMM);

    build_kernel<<<GB, 256>>>(cam, anchors, scales, afeat, tfeat, factors, vis, knn, out, M);
    mlp3_kernel<<<148, 448, SMEM3>>>(
        taf,
        op_w1, op_b1, op_w2, op_b2,
        col_w1, col_b1, col_w2, col_b2,
        cov_w1, cov_b1, cov_w2, cov_b2,
        pf, out, M);
    mlp_mot_kernel<<<296, 256, SMEMM>>>(tafm, mot_w1, mot_b1, mot_w2, mot_b2, mf, out, M);
}

// round 11
// speedup vs baseline: 1.8023x; 1.0990x over previous
#include <cuda_runtime.h>
#include <mma.h>
#include <math.h>

using namespace nvcuda;

#define MAXM 400000

__device__ __align__(256) float g_taf[(size_t)MAXM * 56 + 1024];   // [M][56] tf32, cols 51..55 = 0
__device__ __align__(256) float g_tafm[(size_t)MAXM * 48 + 1024];  // [M][48] tf32
__device__ float g_pf[MAXM + 1024];
__device__ float g_mf[MAXM + 1024];

__device__ __forceinline__ float sigmoidf_(float x) { return 1.f / (1.f + expf(-x)); }
__device__ __forceinline__ float tf32r(float x) { return wmma::__float_to_tf32(x); }

// ================= builder: 2 threads per point, dim-split =================
// h0: feat dims 0..23 ; h1: feat dims 24..31 + tf dims (32..47 of facc)
__global__ __launch_bounds__(256, 3)
void build_kernel(const float* __restrict__ cam,
                  const float* __restrict__ anchors,
                  const float* __restrict__ scales,
                  const float* __restrict__ afeat,
                  const float* __restrict__ tfeat,
                  const float* __restrict__ factors,
                  const int* __restrict__ vis,
                  const int* __restrict__ knn,
                  float* __restrict__ out, int M)
{
    const int tid = threadIdx.x;
    const int m = blockIdx.x * 128 + (tid >> 1);
    const int h = tid & 1;
    if (m >= M) return;
    const int idx = vis[m];

    float4 fc = __ldg(reinterpret_cast<const float4*>(factors + (long long)idx * 4));
    const float tff = fc.x, mf = fc.y, kf = fc.z, pf = fc.w;

    // ---- KNN accumulate (24 dims per thread) ----
    float facc[24];
    #pragma unroll
    for (int i = 0; i < 24; i++) facc[i] = 0.f;

    const int* kp = knn + (long long)idx * 6;
    #pragma unroll 2
    for (int nb = 0; nb < 6; nb++) {
        int nidx = __ldg(kp + nb);
        float4 v[6];
        if (h == 0) {
            const float4* fa = reinterpret_cast<const float4*>(afeat + (long long)nidx * 32);
            #pragma unroll
            for (int q = 0; q < 6; q++) v[q] = __ldg(fa + q);          // feat 0..23
        } else {
            const float4* fa = reinterpret_cast<const float4*>(afeat + (long long)nidx * 32 + 24);
            v[0] = __ldg(fa + 0); v[1] = __ldg(fa + 1);                 // feat 24..31
            const float4* ta = reinterpret_cast<const float4*>(tfeat + (long long)nidx * 256 + 112);
            #pragma unroll
            for (int q = 0; q < 4; q++) v[2 + q] = __ldg(ta + q);       // tf 0..15
        }
        #pragma unroll
        for (int q = 0; q < 6; q++) {
            facc[4*q+0] += v[q].x; facc[4*q+1] += v[q].y;
            facc[4*q+2] += v[q].z; facc[4*q+3] += v[q].w;
        }
    }

    const float wk = (1.f - kf) * (1.f / 6.f);

    if (h == 0) {
        // ---- own feat 0..23, write taf[0..23], tafm[0..23], pf/mf ----
        float4 ov[6];
        const float4* fp = reinterpret_cast<const float4*>(afeat + (long long)idx * 32);
        #pragma unroll
        for (int q = 0; q < 6; q++) ov[q] = __ldg(fp + q);

        float4* tr = reinterpret_cast<float4*>(g_taf + (size_t)m * 56);
        float4* mr = reinterpret_cast<float4*>(g_tafm + (size_t)m * 48);
        #pragma unroll
        for (int q = 0; q < 6; q++) {
            tr[q] = make_float4(tf32r(ov[q].x), tf32r(ov[q].y), tf32r(ov[q].z), tf32r(ov[q].w));
            mr[q] = make_float4(tf32r(fmaf(kf, ov[q].x, wk * facc[4*q+0])),
                                tf32r(fmaf(kf, ov[q].y, wk * facc[4*q+1])),
                                tf32r(fmaf(kf, ov[q].z, wk * facc[4*q+2])),
                                tf32r(fmaf(kf, ov[q].w, wk * facc[4*q+3])));
        }
        g_pf[m] = pf;
        g_mf[m] = mf;
    } else {
        // ---- own feat 24..31, tf, vdn, epilogue ----
        float4 of0, of1, tv[4];
        {
            const float4* fp = reinterpret_cast<const float4*>(afeat + (long long)idx * 32 + 24);
            of0 = __ldg(fp + 0); of1 = __ldg(fp + 1);
            const float4* tp = reinterpret_cast<const float4*>(tfeat + (long long)idx * 256 + 112);
            #pragma unroll
            for (int q = 0; q < 4; q++) tv[q] = __ldg(tp + q);
        }
        float ax = __ldg(anchors + (long long)idx * 3 + 0);
        float ay = __ldg(anchors + (long long)idx * 3 + 1);
        float az = __ldg(anchors + (long long)idx * 3 + 2);
        float vx = ax - cam[3], vy = ay - cam[7], vz = az - cam[11];
        float nrm = sqrtf(vx*vx + vy*vy + vz*vz);
        float inv = 1.f / fmaxf(nrm, 1e-8f);

        // tf scaled
        float ts[16];
        #pragma unroll
        for (int q = 0; q < 4; q++) {
            ts[4*q+0] = tv[q].x * tff; ts[4*q+1] = tv[q].y * tff;
            ts[4*q+2] = tv[q].z * tff; ts[4*q+3] = tv[q].w * tff;
        }

        // taf cols 24..55
        float4* tr = reinterpret_cast<float4*>(g_taf + (size_t)m * 56);
        tr[6] = make_float4(tf32r(of0.x), tf32r(of0.y), tf32r(of0.z), tf32r(of0.w));
        tr[7] = make_float4(tf32r(of1.x), tf32r(of1.y), tf32r(of1.z), tf32r(of1.w));
        tr[8] = make_float4(tf32r(vx*inv), tf32r(vy*inv), tf32r(vz*inv), tf32r(ts[0]));
        tr[9]  = make_float4(tf32r(ts[1]),  tf32r(ts[2]),  tf32r(ts[3]),  tf32r(ts[4]));
        tr[10] = make_float4(tf32r(ts[5]),  tf32r(ts[6]),  tf32r(ts[7]),  tf32r(ts[8]));
        tr[11] = make_float4(tf32r(ts[9]),  tf32r(ts[10]), tf32r(ts[11]), tf32r(ts[12]));
        tr[12] = make_float4(tf32r(ts[13]), tf32r(ts[14]), tf32r(ts[15]), 0.f);
        tr[13] = make_float4(0.f, 0.f, 0.f, 0.f);

        // tafm cols 24..47: dims 24..31 from of0/of1 (facc[0..7]), 32..47 from ts (facc[8..23])
        float4* mr = reinterpret_cast<float4*>(g_tafm + (size_t)m * 48);
        mr[6] = make_float4(tf32r(fmaf(kf, of0.x, wk*facc[0])), tf32r(fmaf(kf, of0.y, wk*facc[1])),
                            tf32r(fmaf(kf, of0.z, wk*facc[2])), tf32r(fmaf(kf, of0.w, wk*facc[3])));
        mr[7] = make_float4(tf32r(fmaf(kf, of1.x, wk*facc[4])), tf32r(fmaf(kf, of1.y, wk*facc[5])),
                            tf32r(fmaf(kf, of1.z, wk*facc[6])), tf32r(fmaf(kf, of1.w, wk*facc[7])));
        #pragma unroll
        for (int q = 0; q < 4; q++)
            mr[8 + q] = make_float4(
                tf32r(fmaf(kf, ts[4*q+0], wk*facc[8 + 4*q+0])),
                tf32r(fmaf(kf, ts[4*q+1], wk*facc[8 + 4*q+1])),
                tf32r(fmaf(kf, ts[4*q+2], wk*facc[8 + 4*q+2])),
                tf32r(fmaf(kf, ts[4*q+3], wk*facc[8 + 4*q+3])));

        // epilogue columns
        float* om = out + (long long)M * 110 + (long long)m * 50;
        const float* sp = scales + (long long)idx * 6;
        om[37] = expf(__ldg(sp + 0));
        om[38] = expf(__ldg(sp + 1));
        om[39] = expf(__ldg(sp + 2));
        om[40] = expf(__ldg(sp + 3)) * pf;
        om[41] = expf(__ldg(sp + 4)) * pf;
        om[42] = expf(__ldg(sp + 5)) * pf;
        om[43] = tff; om[44] = mf; om[45] = kf; om[46] = pf;
        om[47] = ax; om[48] = ay; om[49] = az;
    }
}

// ================= fused op+col+cov wmma kernel, per-slice, 15 warps =================
#define W1S 192
#define W2S 128
#define XS3 60
#define HS3 84
#define OW1_3 0
#define OW2_3 10752
#define OB1R_3 18944          // 16 x 192 replicated b1
#define OB2_3  22016          // 128 raw b2 (epilogue)
#define OWRP_3 22144
#define SLAB_3 2304           // 16*60 + 16*84
#define NW3 15
#define NT3 (NW3 * 32)
#define SMEM3_FLOATS (OWRP_3 + NW3 * SLAB_3)

__global__ __launch_bounds__(NT3, 1)
void mlp3_kernel(const float* __restrict__ xin,
                 const float* __restrict__ op_w1,  const float* __restrict__ op_b1,
                 const float* __restrict__ op_w2,  const float* __restrict__ op_b2,
                 const float* __restrict__ col_w1, const float* __restrict__ col_b1,
                 const float* __restrict__ col_w2, const float* __restrict__ col_b2,
                 const float* __restrict__ cov_w1, const float* __restrict__ cov_b1,
                 const float* __restrict__ cov_w2, const float* __restrict__ cov_b2,
                 const float* __restrict__ pfv,
                 float* __restrict__ out, int M)
{
    extern __shared__ float S[];
    const int tid = threadIdx.x;
    const int warp = tid >> 5;
    const int lane = tid & 31;

    for (int i = tid; i < 56 * W1S; i += NT3) {
        int row = i / W1S, c = i - row * W1S;
        int sel = c >> 6, cc = c & 63;
        float v = 0.f;
        if (row < 51)
            v = (sel == 0) ? op_w1[row * 64 + cc]
              : (sel == 1) ? col_w1[row * 64 + cc]
                           : cov_w1[row * 64 + cc];
        S[OW1_3 + i] = tf32r(v);
    }
    for (int i = tid; i < 64 * W2S; i += NT3) {
        int j = i >> 7, c = i & 127;
        float v = 0.f;
        if (c < 16)       { if (c < 10)      v = op_w2 [j * 10 + c]; }
        else if (c < 48)  { if (c - 16 < 30) v = col_w2[j * 30 + (c - 16)]; }
        else              { if (c - 48 < 70) v = cov_w2[j * 70 + (c - 48)]; }
        S[OW2_3 + i] = tf32r(v);
    }
    if (tid < W1S) {
        int sel = tid >> 6, cc = tid & 63;
        S[OB1R_3 + tid] = (sel == 0) ? op_b1[cc] : (sel == 1) ? col_b1[cc] : cov_b1[cc];
    }
    if (tid < W2S) {
        float v = 0.f;
        if (tid < 16)      { if (tid < 10)      v = op_b2 [tid]; }
        else if (tid < 48) { if (tid - 16 < 30) v = col_b2[tid - 16]; }
        else               { if (tid - 48 < 70) v = cov_b2[tid - 48]; }
        S[OB2_3 + tid] = v;
    }
    __syncthreads();
    for (int i = tid; i < 16 * W1S; i += NT3)
        if (i >= W1S) S[OB1R_3 + i] = S[OB1R_3 + (i % W1S)];
    __syncthreads();

    float* Xp = S + OWRP_3 + warp * SLAB_3;
    float* Hp = Xp + 16 * XS3;
    const int tiles = (M + 15) >> 4;

    for (int t = blockIdx.x * NW3 + warp; t < tiles; t += gridDim.x * NW3) {
        {
            const float* src = xin + (size_t)t * 16 * 56;
            #pragma unroll
            for (int it = 0; it < 7; it++) {
                int e = lane * 4 + it * 128;
                float4 v = __ldg(reinterpret_cast<const float4*>(src + e));
                int row = e / 56, c = e - row * 56;
                *reinterpret_cast<float4*>(Xp + row * XS3 + c) = v;
            }
        }
        __syncwarp();

        int p = lane >> 1, half = lane & 1;
        size_t m = (size_t)t * 16 + p;
        bool valid = (m < (size_t)M);
        float pf = valid ? __ldg(pfv + m) : 0.f;
        float* omk = out + m * 110;

        #pragma unroll 1
        for (int s = 0; s < 3; s++) {
            wmma::fragment<wmma::accumulator, 16, 16, 8, float> c1[4];
            #pragma unroll
            for (int n = 0; n < 4; n++)
                wmma::load_matrix_sync(c1[n], S + OB1R_3 + s * 64 + n * 16, W1S, wmma::mem_row_major);
            #pragma unroll 1
            for (int k = 0; k < 7; k++) {
                wmma::fragment<wmma::matrix_a, 16, 16, 8, wmma::precision::tf32, wmma::row_major> af;
                wmma::load_matrix_sync(af, Xp + k * 8, XS3);
                #pragma unroll
                for (int n = 0; n < 4; n++) {
                    wmma::fragment<wmma::matrix_b, 16, 16, 8, wmma::precision::tf32, wmma::row_major> bf;
                    wmma::load_matrix_sync(bf, S + OW1_3 + (k * 8) * W1S + s * 64 + n * 16, W1S);
                    wmma::mma_sync(c1[n], af, bf, c1[n]);
                }
            }
            #pragma unroll
            for (int n = 0; n < 4; n++) {
                #pragma unroll
                for (int i = 0; i < c1[n].num_elements; i++)
                    c1[n].x[i] = tf32r(fmaxf(c1[n].x[i], 0.f));
                wmma::store_matrix_sync(Hp + n * 16, c1[n], HS3, wmma::mem_row_major);
            }
            __syncwarp();

            if (s == 0) {
                wmma::fragment<wmma::accumulator, 16, 16, 8, float> c2;
                wmma::fill_fragment(c2, 0.f);
                #pragma unroll 1
                for (int k = 0; k < 8; k++) {
                    wmma::fragment<wmma::matrix_a, 16, 16, 8, wmma::precision::tf32, wmma::row_major> af;
                    wmma::load_matrix_sync(af, Hp + k * 8, HS3);
                    wmma::fragment<wmma::matrix_b, 16, 16, 8, wmma::precision::tf32, wmma::row_major> bf;
                    wmma::load_matrix_sync(bf, S + OW2_3 + (k * 8) * W2S + 0, W2S);
                    wmma::mma_sync(c2, af, bf, c2);
                }
                __syncwarp();
                wmma::store_matrix_sync(Hp, c2, HS3, wmma::mem_row_major);
                __syncwarp();
                if (valid) {
                    const float* cr = Hp + p * HS3;
                    #pragma unroll
                    for (int k = half * 5; k < half * 5 + 5; k++)
                        omk[k * 11] = tanhf(cr[k] + S[OB2_3 + k]) * pf;
                }
            } else if (s == 1) {
                wmma::fragment<wmma::accumulator, 16, 16, 8, float> c2[2];
                #pragma unroll
                for (int n = 0; n < 2; n++) wmma::fill_fragment(c2[n], 0.f);
                #pragma unroll 1
                for (int k = 0; k < 8; k++) {
                    wmma::fragment<wmma::matrix_a, 16, 16, 8, wmma::precision::tf32, wmma::row_major> af;
                    wmma::load_matrix_sync(af, Hp + k * 8, HS3);
                    #pragma unroll
                    for (int n = 0; n < 2; n++) {
                        wmma::fragment<wmma::matrix_b, 16, 16, 8, wmma::precision::tf32, wmma::row_major> bf;
                        wmma::load_matrix_sync(bf, S + OW2_3 + (k * 8) * W2S + 16 + n * 16, W2S);
                        wmma::mma_sync(c2[n], af, bf, c2[n]);
                    }
                }
                __syncwarp();
                #pragma unroll
                for (int n = 0; n < 2; n++)
                    wmma::store_matrix_sync(Hp + n * 16, c2[n], HS3, wmma::mem_row_major);
                __syncwarp();
                if (valid) {
                    const float* cr = Hp + p * HS3;
                    #pragma unroll
                    for (int k = half * 15; k < half * 15 + 15; k++) {
                        int kd = k / 3;
                        omk[kd * 11 + 1 + (k - kd * 3)] = sigmoidf_(cr[k] + S[OB2_3 + 16 + k]);
                    }
                }
            } else {
                wmma::fragment<wmma::accumulator, 16, 16, 8, float> c2[5];
                #pragma unroll
                for (int n = 0; n < 5; n++) wmma::fill_fragment(c2[n], 0.f);
                #pragma unroll 1
                for (int k = 0; k < 8; k++) {
                    wmma::fragment<wmma::matrix_a, 16, 16, 8, wmma::precision::tf32, wmma::row_major> af;
                    wmma::load_matrix_sync(af, Hp + k * 8, HS3);
                    #pragma unroll
                    for (int n = 0; n < 5; n++) {
                        wmma::fragment<wmma::matrix_b, 16, 16, 8, wmma::precision::tf32, wmma::row_major> bf;
                        wmma::load_matrix_sync(bf, S + OW2_3 + (k * 8) * W2S + 48 + n * 16, W2S);
                        wmma::mma_sync(c2[n], af, bf, c2[n]);
                    }
                }
                __syncwarp();
                #pragma unroll
                for (int n = 0; n < 5; n++)
                    wmma::store_matrix_sync(Hp + n * 16, c2[n], HS3, wmma::mem_row_major);
                __syncwarp();
                if (valid) {
                    const float* cr = Hp + p * HS3;
                    #pragma unroll
                    for (int k = half * 35; k < half * 35 + 35; k++) {
                        int kd = k / 7;
                        omk[kd * 11 + 4 + (k - kd * 7)] = cr[k] + S[OB2_3 + 48 + k];
                    }
                }
            }
            __syncwarp();
        }
    }
}

// ================= motion wmma kernel =================
#define MXS 52
#define MHS 68
#define OW1_M 0
#define OW2_M 3072
#define OB1R_M 6144
#define OB2R_M 7168
#define OWRP_M 7936
#define SLAB_M 1920
#define SMEMM_FLOATS (OWRP_M + 8 * SLAB_M)

__global__ __launch_bounds__(256, 2)
void mlp_mot_kernel(const float* __restrict__ xin,
                    const float* __restrict__ w1g, const float* __restrict__ b1g,
                    const float* __restrict__ w2g, const float* __restrict__ b2g,
                    const float* __restrict__ mfv,
                    float* __restrict__ out, int M)
{
    extern __shared__ float S[];
    const int tid = threadIdx.x;
    const int warp = tid >> 5;
    const int lane = tid & 31;

    for (int i = tid; i < 48 * 64; i += 256) S[OW1_M + i] = tf32r(w1g[i]);
    for (int i = tid; i < 64 * 48; i += 256) {
        int j = i / 48, k = i - j * 48;
        S[OW2_M + i] = (k < 37) ? tf32r(w2g[j * 37 + k]) : 0.f;
    }
    if (tid < 64) {
        float acc = b1g[tid];
        #pragma unroll
        for (int t = 0; t < 8; t++) {
            float ang = exp2f((float)t) * 1.5707963267948966f;
            acc = fmaf(sinf(ang), w1g[(48 + t) * 64 + tid], acc);
            acc = fmaf(cosf(ang), w1g[(56 + t) * 64 + tid], acc);
        }
        S[OB1R_M + tid] = acc;
    }
    if (tid < 48) S[OB2R_M + tid] = (tid < 37) ? b2g[tid] : 0.f;
    __syncthreads();
    for (int i = tid; i < 16 * 64; i += 256)
        if (i >= 64) S[OB1R_M + i] = S[OB1R_M + (i & 63)];
    for (int i = tid; i < 16 * 48; i += 256)
        if (i >= 48) S[OB2R_M + i] = S[OB2R_M + (i % 48)];
    __syncthreads();

    float* Xp = S + OWRP_M + warp * SLAB_M;
    float* Hp = Xp + 16 * MXS;
    const int tiles = (M + 15) >> 4;

    for (int t = blockIdx.x * 8 + warp; t < tiles; t += gridDim.x * 8) {
        {
            const float* src = xin + (size_t)t * 16 * 48;
            #pragma unroll
            for (int it = 0; it < 6; it++) {
                int e = lane * 4 + it * 128;
                float4 v = __ldg(reinterpret_cast<const float4*>(src + e));
                int row = e / 48, c = e - row * 48;
                *reinterpret_cast<float4*>(Xp + row * MXS + c) = v;
            }
        }
        __syncwarp();

        wmma::fragment<wmma::accumulator, 16, 16, 8, float> c1[4];
        #pragma unroll
        for (int n = 0; n < 4; n++)
            wmma::load_matrix_sync(c1[n], S + OB1R_M + n * 16, 64, wmma::mem_row_major);
        #pragma unroll 1
        for (int k = 0; k < 6; k++) {
            wmma::fragment<wmma::matrix_a, 16, 16, 8, wmma::precision::tf32, wmma::row_major> af;
            wmma::load_matrix_sync(af, Xp + k * 8, MXS);
            #pragma unroll
            for (int n = 0; n < 4; n++) {
                wmma::fragment<wmma::matrix_b, 16, 16, 8, wmma::precision::tf32, wmma::row_major> bf;
                wmma::load_matrix_sync(bf, S + OW1_M + k * 8 * 64 + n * 16, 64);
                wmma::mma_sync(c1[n], af, bf, c1[n]);
            }
        }
        #pragma unroll
        for (int n = 0; n < 4; n++) {
            #pragma unroll
            for (int i = 0; i < c1[n].num_elements; i++)
                c1[n].x[i] = tf32r(fmaxf(c1[n].x[i], 0.f));
            wmma::store_matrix_sync(Hp + n * 16, c1[n], MHS, wmma::mem_row_major);
        }
        __syncwarp();

        wmma::fragment<wmma::accumulator, 16, 16, 8, float> c2[3];
        #pragma unroll
        for (int n = 0; n < 3; n++)
            wmma::load_matrix_sync(c2[n], S + OB2R_M + n * 16, 48, wmma::mem_row_major);
        #pragma unroll 1
        for (int k = 0; k < 8; k++) {
            wmma::fragment<wmma::matrix_a, 16, 16, 8, wmma::precision::tf32, wmma::row_major> af;
            wmma::load_matrix_sync(af, Hp + k * 8, MHS);
            #pragma unroll
            for (int n = 0; n < 3; n++) {
                wmma::fragment<wmma::matrix_b, 16, 16, 8, wmma::precision::tf32, wmma::row_major> bf;
                wmma::load_matrix_sync(bf, S + OW2_M + k * 8 * 48 + n * 16, 48);
                wmma::mma_sync(c2[n], af, bf, c2[n]);
            }
        }
        __syncwarp();
        #pragma unroll
        for (int n = 0; n < 3; n++)
            wmma::store_matrix_sync(Xp + n * 16, c2[n], MXS, wmma::mem_row_major);
        __syncwarp();

        {
            int p = lane >> 1, half = lane & 1;
            size_t m = (size_t)t * 16 + p;
            if (m < (size_t)M) {
                float mfs = __ldg(mfv + m);
                float* om = out + (size_t)M * 110 + m * 50;
                const float* c2r = Xp + p * MXS;
                int k0 = half ? 19 : 0, k1 = half ? 37 : 19;
                for (int k = k0; k < k1; k++)
                    om[k] = c2r[k] * mfs;
            }
        }
        __syncwarp();
    }
}

// ================= launch =================
extern "C" void kernel_launch(void* const* d_in, const int* in_sizes, int n_in,
                              void* d_out, int out_size)
{
    const float* cam     = (const float*)d_in[0];
    const float* anchors = (const float*)d_in[1];
    const float* scales  = (const float*)d_in[2];
    const float* afeat   = (const float*)d_in[3];
    const float* tfeat   = (const float*)d_in[4];
    const float* factors = (const float*)d_in[5];
    const float* op_w1   = (const float*)d_in[6];
    const float* op_b1   = (const float*)d_in[7];
    const float* op_w2   = (const float*)d_in[8];
    const float* op_b2   = (const float*)d_in[9];
    const float* col_w1  = (const float*)d_in[10];
    const float* col_b1  = (const float*)d_in[11];
    const float* col_w2  = (const float*)d_in[12];
    const float* col_b2  = (const float*)d_in[13];
    const float* cov_w1  = (const float*)d_in[14];
    const float* cov_b1  = (const float*)d_in[15];
    const float* cov_w2  = (const float*)d_in[16];
    const float* cov_b2  = (const float*)d_in[17];
    const float* mot_w1  = (const float*)d_in[18];
    const float* mot_b1  = (const float*)d_in[19];
    const float* mot_w2  = (const float*)d_in[20];
    const float* mot_b2  = (const float*)d_in[21];
    const int*   vis     = (const int*)d_in[22];
    const int*   knn     = (const int*)d_in[23];

    int M = in_sizes[22];
    float* out = (float*)d_out;

    float *taf, *tafm, *pf, *mf;
    cudaGetSymbolAddress((void**)&taf,  g_taf);
    cudaGetSymbolAddress((void**)&tafm, g_tafm);
    cudaGetSymbolAddress((void**)&pf,   g_pf);
    cudaGetSymbolAddress((void**)&mf,   g_mf);

    const int GB = (M + 127) / 128;   // 2 threads/point

    const int SMEM3 = SMEM3_FLOATS * 4;   // 226,816 B
    const int SMEMM = SMEMM_FLOATS * 4;
    cudaFuncSetAttribute(mlp3_kernel,    cudaFuncAttributeMaxDynamicSharedMemorySize, SMEM3);
    cudaFuncSetAttribute(mlp_mot_kernel, cudaFuncAttributeMaxDynamicSharedMemorySize, SMEMM);

    build_kernel<<<GB, 256>>>(cam, anchors, scales, afeat, tfeat, factors, vis, knn, out, M);
    mlp3_kernel<<<148, NT3, SMEM3>>>(
        taf,
        op_w1, op_b1, op_w2, op_b2,
        col_w1, col_b1, col_w2, col_b2,
        cov_w1, cov_b1, cov_w2, cov_b2,
        pf, out, M);
    mlp_mot_kernel<<<296, 256, SMEMM>>>(tafm, mot_w1, mot_b1, mot_w2, mot_b2, mf, out, M);
}

// round 12
// speedup vs baseline: 1.8436x; 1.0229x over previous
#include <cuda_runtime.h>
#include <mma.h>
#include <math.h>

using namespace nvcuda;

#define MAXM 400000

__device__ __align__(256) float g_taf[(size_t)MAXM * 56 + 4096];   // [M][56] tf32, cols 51..55 = 0
__device__ __align__(256) float g_tafm[(size_t)MAXM * 48 + 4096];  // [M][48] tf32
__device__ float g_pf[MAXM + 1024];
__device__ float g_mf[MAXM + 1024];

__device__ __forceinline__ float sigmoidf_(float x) { return 1.f / (1.f + expf(-x)); }
__device__ __forceinline__ float tf32r(float x) { return wmma::__float_to_tf32(x); }

// ================= builder: 2 threads per point, dim-split (R11, committed) =================
__global__ __launch_bounds__(256, 3)
void build_kernel(const float* __restrict__ cam,
                  const float* __restrict__ anchors,
                  const float* __restrict__ scales,
                  const float* __restrict__ afeat,
                  const float* __restrict__ tfeat,
                  const float* __restrict__ factors,
                  const int* __restrict__ vis,
                  const int* __restrict__ knn,
                  float* __restrict__ out, int M)
{
    const int tid = threadIdx.x;
    const int m = blockIdx.x * 128 + (tid >> 1);
    const int h = tid & 1;
    if (m >= M) return;
    const int idx = vis[m];

    float4 fc = __ldg(reinterpret_cast<const float4*>(factors + (long long)idx * 4));
    const float tff = fc.x, mf = fc.y, kf = fc.z, pf = fc.w;

    float facc[24];
    #pragma unroll
    for (int i = 0; i < 24; i++) facc[i] = 0.f;

    const int* kp = knn + (long long)idx * 6;
    #pragma unroll 2
    for (int nb = 0; nb < 6; nb++) {
        int nidx = __ldg(kp + nb);
        float4 v[6];
        if (h == 0) {
            const float4* fa = reinterpret_cast<const float4*>(afeat + (long long)nidx * 32);
            #pragma unroll
            for (int q = 0; q < 6; q++) v[q] = __ldg(fa + q);
        } else {
            const float4* fa = reinterpret_cast<const float4*>(afeat + (long long)nidx * 32 + 24);
            v[0] = __ldg(fa + 0); v[1] = __ldg(fa + 1);
            const float4* ta = reinterpret_cast<const float4*>(tfeat + (long long)nidx * 256 + 112);
            #pragma unroll
            for (int q = 0; q < 4; q++) v[2 + q] = __ldg(ta + q);
        }
        #pragma unroll
        for (int q = 0; q < 6; q++) {
            facc[4*q+0] += v[q].x; facc[4*q+1] += v[q].y;
            facc[4*q+2] += v[q].z; facc[4*q+3] += v[q].w;
        }
    }

    const float wk = (1.f - kf) * (1.f / 6.f);

    if (h == 0) {
        float4 ov[6];
        const float4* fp = reinterpret_cast<const float4*>(afeat + (long long)idx * 32);
        #pragma unroll
        for (int q = 0; q < 6; q++) ov[q] = __ldg(fp + q);

        float4* tr = reinterpret_cast<float4*>(g_taf + (size_t)m * 56);
        float4* mr = reinterpret_cast<float4*>(g_tafm + (size_t)m * 48);
        #pragma unroll
        for (int q = 0; q < 6; q++) {
            tr[q] = make_float4(tf32r(ov[q].x), tf32r(ov[q].y), tf32r(ov[q].z), tf32r(ov[q].w));
            mr[q] = make_float4(tf32r(fmaf(kf, ov[q].x, wk * facc[4*q+0])),
                                tf32r(fmaf(kf, ov[q].y, wk * facc[4*q+1])),
                                tf32r(fmaf(kf, ov[q].z, wk * facc[4*q+2])),
                                tf32r(fmaf(kf, ov[q].w, wk * facc[4*q+3])));
        }
        g_pf[m] = pf;
        g_mf[m] = mf;
    } else {
        float4 of0, of1, tv[4];
        {
            const float4* fp = reinterpret_cast<const float4*>(afeat + (long long)idx * 32 + 24);
            of0 = __ldg(fp + 0); of1 = __ldg(fp + 1);
            const float4* tp = reinterpret_cast<const float4*>(tfeat + (long long)idx * 256 + 112);
            #pragma unroll
            for (int q = 0; q < 4; q++) tv[q] = __ldg(tp + q);
        }
        float ax = __ldg(anchors + (long long)idx * 3 + 0);
        float ay = __ldg(anchors + (long long)idx * 3 + 1);
        float az = __ldg(anchors + (long long)idx * 3 + 2);
        float vx = ax - cam[3], vy = ay - cam[7], vz = az - cam[11];
        float nrm = sqrtf(vx*vx + vy*vy + vz*vz);
        float inv = 1.f / fmaxf(nrm, 1e-8f);

        float ts[16];
        #pragma unroll
        for (int q = 0; q < 4; q++) {
            ts[4*q+0] = tv[q].x * tff; ts[4*q+1] = tv[q].y * tff;
            ts[4*q+2] = tv[q].z * tff; ts[4*q+3] = tv[q].w * tff;
        }

        float4* tr = reinterpret_cast<float4*>(g_taf + (size_t)m * 56);
        tr[6] = make_float4(tf32r(of0.x), tf32r(of0.y), tf32r(of0.z), tf32r(of0.w));
        tr[7] = make_float4(tf32r(of1.x), tf32r(of1.y), tf32r(of1.z), tf32r(of1.w));
        tr[8] = make_float4(tf32r(vx*inv), tf32r(vy*inv), tf32r(vz*inv), tf32r(ts[0]));
        tr[9]  = make_float4(tf32r(ts[1]),  tf32r(ts[2]),  tf32r(ts[3]),  tf32r(ts[4]));
        tr[10] = make_float4(tf32r(ts[5]),  tf32r(ts[6]),  tf32r(ts[7]),  tf32r(ts[8]));
        tr[11] = make_float4(tf32r(ts[9]),  tf32r(ts[10]), tf32r(ts[11]), tf32r(ts[12]));
        tr[12] = make_float4(tf32r(ts[13]), tf32r(ts[14]), tf32r(ts[15]), 0.f);
        tr[13] = make_float4(0.f, 0.f, 0.f, 0.f);

        float4* mr = reinterpret_cast<float4*>(g_tafm + (size_t)m * 48);
        mr[6] = make_float4(tf32r(fmaf(kf, of0.x, wk*facc[0])), tf32r(fmaf(kf, of0.y, wk*facc[1])),
                            tf32r(fmaf(kf, of0.z, wk*facc[2])), tf32r(fmaf(kf, of0.w, wk*facc[3])));
        mr[7] = make_float4(tf32r(fmaf(kf, of1.x, wk*facc[4])), tf32r(fmaf(kf, of1.y, wk*facc[5])),
                            tf32r(fmaf(kf, of1.z, wk*facc[6])), tf32r(fmaf(kf, of1.w, wk*facc[7])));
        #pragma unroll
        for (int q = 0; q < 4; q++)
            mr[8 + q] = make_float4(
                tf32r(fmaf(kf, ts[4*q+0], wk*facc[8 + 4*q+0])),
                tf32r(fmaf(kf, ts[4*q+1], wk*facc[8 + 4*q+1])),
                tf32r(fmaf(kf, ts[4*q+2], wk*facc[8 + 4*q+2])),
                tf32r(fmaf(kf, ts[4*q+3], wk*facc[8 + 4*q+3])));

        float* om = out + (long long)M * 110 + (long long)m * 50;
        const float* sp = scales + (long long)idx * 6;
        om[37] = expf(__ldg(sp + 0));
        om[38] = expf(__ldg(sp + 1));
        om[39] = expf(__ldg(sp + 2));
        om[40] = expf(__ldg(sp + 3)) * pf;
        om[41] = expf(__ldg(sp + 4)) * pf;
        om[42] = expf(__ldg(sp + 5)) * pf;
        om[43] = tff; om[44] = mf; om[45] = kf; om[46] = pf;
        om[47] = ax; om[48] = ay; om[49] = az;
    }
}

// ================= mlp3: 2 M-tiles/warp, A-frags in registers =================
// W1c [56x192] (op|col|cov), W2c [64x128] (op@0 | col@16 | cov@48)
// Per-warp slab: [32 x 84] union (X -> H -> C2), contiguous rows 0..31
#define W1S 192
#define W2S 128
#define HS3 84
#define OW1_3 0
#define OW2_3 10752
#define OB1R_3 18944          // 16 x 192 replicated b1
#define OB2_3  22016          // 128 raw b2 (epilogue)
#define OWRP_3 22144
#define SLAB_3 2688           // 32*84
#define NW3 13
#define NT3 (NW3 * 32)
#define SMEM3_FLOATS (OWRP_3 + NW3 * SLAB_3)   // 57088 -> 228352 B

__global__ __launch_bounds__(NT3, 1)
void mlp3_kernel(const float* __restrict__ xin,
                 const float* __restrict__ op_w1,  const float* __restrict__ op_b1,
                 const float* __restrict__ op_w2,  const float* __restrict__ op_b2,
                 const float* __restrict__ col_w1, const float* __restrict__ col_b1,
                 const float* __restrict__ col_w2, const float* __restrict__ col_b2,
                 const float* __restrict__ cov_w1, const float* __restrict__ cov_b1,
                 const float* __restrict__ cov_w2, const float* __restrict__ cov_b2,
                 const float* __restrict__ pfv,
                 float* __restrict__ out, int M)
{
    extern __shared__ float S[];
    const int tid = threadIdx.x;
    const int warp = tid >> 5;
    const int lane = tid & 31;

    // ---- stage combined weights ----
    for (int i = tid; i < 56 * W1S; i += NT3) {
        int row = i / W1S, c = i - row * W1S;
        int sel = c >> 6, cc = c & 63;
        float v = 0.f;
        if (row < 51)
            v = (sel == 0) ? op_w1[row * 64 + cc]
              : (sel == 1) ? col_w1[row * 64 + cc]
                           : cov_w1[row * 64 + cc];
        S[OW1_3 + i] = tf32r(v);
    }
    for (int i = tid; i < 64 * W2S; i += NT3) {
        int j = i >> 7, c = i & 127;
        float v = 0.f;
        if (c < 16)       { if (c < 10)      v = op_w2 [j * 10 + c]; }
        else if (c < 48)  { if (c - 16 < 30) v = col_w2[j * 30 + (c - 16)]; }
        else              { if (c - 48 < 70) v = cov_w2[j * 70 + (c - 48)]; }
        S[OW2_3 + i] = tf32r(v);
    }
    if (tid < W1S) {
        int sel = tid >> 6, cc = tid & 63;
        S[OB1R_3 + tid] = (sel == 0) ? op_b1[cc] : (sel == 1) ? col_b1[cc] : cov_b1[cc];
    }
    if (tid < W2S) {
        float v = 0.f;
        if (tid < 16)      { if (tid < 10)      v = op_b2 [tid]; }
        else if (tid < 48) { if (tid - 16 < 30) v = col_b2[tid - 16]; }
        else               { if (tid - 48 < 70) v = cov_b2[tid - 48]; }
        S[OB2_3 + tid] = v;
    }
    __syncthreads();
    for (int i = tid; i < 16 * W1S; i += NT3)
        if (i >= W1S) S[OB1R_3 + i] = S[OB1R_3 + (i % W1S)];
    __syncthreads();

    float* Xp = S + OWRP_3 + warp * SLAB_3;       // [32 x 84]
    const int tiles32 = (M + 31) >> 5;

    for (int t = blockIdx.x * NW3 + warp; t < tiles32; t += gridDim.x * NW3) {
        // ---- stage X [32x56] coalesced -> stride 84 ----
        {
            const float* src = xin + (size_t)t * 32 * 56;
            #pragma unroll
            for (int it = 0; it < 14; it++) {
                int e = lane * 4 + it * 128;
                float4 v = __ldg(reinterpret_cast<const float4*>(src + e));
                int row = e / 56, c = e - row * 56;
                *reinterpret_cast<float4*>(Xp + row * HS3 + c) = v;
            }
        }
        __syncwarp();

        // ---- load all A-fragments to registers (X region becomes dead) ----
        wmma::fragment<wmma::matrix_a, 16, 16, 8, wmma::precision::tf32, wmma::row_major> af[2][7];
        #pragma unroll
        for (int k = 0; k < 7; k++) {
            wmma::load_matrix_sync(af[0][k], Xp + k * 8, HS3);
            wmma::load_matrix_sync(af[1][k], Xp + 16 * HS3 + k * 8, HS3);
        }
        __syncwarp();

        size_t mlane = (size_t)t * 32 + lane;
        bool valid = (mlane < (size_t)M);
        float pf = valid ? __ldg(pfv + mlane) : 0.f;
        float* omk = out + mlane * 110;
        const float* cr = Xp + lane * HS3;      // lane's row in the slab

        #pragma unroll 1
        for (int s = 0; s < 3; s++) {
            // ---- GEMM1 slice: 2 tiles x 4 n, B amortized, A from regs ----
            wmma::fragment<wmma::accumulator, 16, 16, 8, float> c1[2][4];
            #pragma unroll
            for (int n = 0; n < 4; n++) {
                wmma::load_matrix_sync(c1[0][n], S + OB1R_3 + s * 64 + n * 16, W1S, wmma::mem_row_major);
                wmma::load_matrix_sync(c1[1][n], S + OB1R_3 + s * 64 + n * 16, W1S, wmma::mem_row_major);
            }
            #pragma unroll
            for (int k = 0; k < 7; k++) {
                #pragma unroll
                for (int n = 0; n < 4; n++) {
                    wmma::fragment<wmma::matrix_b, 16, 16, 8, wmma::precision::tf32, wmma::row_major> bf;
                    wmma::load_matrix_sync(bf, S + OW1_3 + (k * 8) * W1S + s * 64 + n * 16, W1S);
                    wmma::mma_sync(c1[0][n], af[0][k], bf, c1[0][n]);
                    wmma::mma_sync(c1[1][n], af[1][k], bf, c1[1][n]);
                }
            }
            // relu + round -> H overwrites slab
            #pragma unroll
            for (int tt = 0; tt < 2; tt++)
                #pragma unroll
                for (int n = 0; n < 4; n++) {
                    #pragma unroll
                    for (int i = 0; i < c1[tt][n].num_elements; i++)
                        c1[tt][n].x[i] = tf32r(fmaxf(c1[tt][n].x[i], 0.f));
                    wmma::store_matrix_sync(Xp + tt * 16 * HS3 + n * 16, c1[tt][n], HS3, wmma::mem_row_major);
                }
            __syncwarp();

            // ---- GEMM2 slice ----
            if (s == 0) {
                wmma::fragment<wmma::accumulator, 16, 16, 8, float> c2[2];
                #pragma unroll
                for (int tt = 0; tt < 2; tt++) wmma::fill_fragment(c2[tt], 0.f);
                #pragma unroll 1
                for (int k = 0; k < 8; k++) {
                    wmma::fragment<wmma::matrix_a, 16, 16, 8, wmma::precision::tf32, wmma::row_major> a0, a1;
                    wmma::load_matrix_sync(a0, Xp + k * 8, HS3);
                    wmma::load_matrix_sync(a1, Xp + 16 * HS3 + k * 8, HS3);
                    wmma::fragment<wmma::matrix_b, 16, 16, 8, wmma::precision::tf32, wmma::row_major> bf;
                    wmma::load_matrix_sync(bf, S + OW2_3 + (k * 8) * W2S + 0, W2S);
                    wmma::mma_sync(c2[0], a0, bf, c2[0]);
                    wmma::mma_sync(c2[1], a1, bf, c2[1]);
                }
                __syncwarp();
                wmma::store_matrix_sync(Xp, c2[0], HS3, wmma::mem_row_major);
                wmma::store_matrix_sync(Xp + 16 * HS3, c2[1], HS3, wmma::mem_row_major);
                __syncwarp();
                if (valid) {
                    #pragma unroll
                    for (int k = 0; k < 10; k++)
                        omk[k * 11] = tanhf(cr[k] + S[OB2_3 + k]) * pf;
                }
            } else if (s == 1) {
                wmma::fragment<wmma::accumulator, 16, 16, 8, float> c2[2][2];
                #pragma unroll
                for (int tt = 0; tt < 2; tt++)
                    #pragma unroll
                    for (int n = 0; n < 2; n++) wmma::fill_fragment(c2[tt][n], 0.f);
                #pragma unroll 1
                for (int k = 0; k < 8; k++) {
                    wmma::fragment<wmma::matrix_a, 16, 16, 8, wmma::precision::tf32, wmma::row_major> a0, a1;
                    wmma::load_matrix_sync(a0, Xp + k * 8, HS3);
                    wmma::load_matrix_sync(a1, Xp + 16 * HS3 + k * 8, HS3);
                    #pragma unroll
                    for (int n = 0; n < 2; n++) {
                        wmma::fragment<wmma::matrix_b, 16, 16, 8, wmma::precision::tf32, wmma::row_major> bf;
                        wmma::load_matrix_sync(bf, S + OW2_3 + (k * 8) * W2S + 16 + n * 16, W2S);
                        wmma::mma_sync(c2[0][n], a0, bf, c2[0][n]);
                        wmma::mma_sync(c2[1][n], a1, bf, c2[1][n]);
                    }
                }
                __syncwarp();
                #pragma unroll
                for (int tt = 0; tt < 2; tt++)
                    #pragma unroll
                    for (int n = 0; n < 2; n++)
                        wmma::store_matrix_sync(Xp + tt * 16 * HS3 + n * 16, c2[tt][n], HS3, wmma::mem_row_major);
                __syncwarp();
                if (valid) {
                    #pragma unroll
                    for (int k = 0; k < 30; k++) {
                        int kd = k / 3;
                        omk[kd * 11 + 1 + (k - kd * 3)] = sigmoidf_(cr[k] + S[OB2_3 + 16 + k]);
                    }
                }
            } else {
                wmma::fragment<wmma::accumulator, 16, 16, 8, float> c2[2][5];
                #pragma unroll
                for (int tt = 0; tt < 2; tt++)
                    #pragma unroll
                    for (int n = 0; n < 5; n++) wmma::fill_fragment(c2[tt][n], 0.f);
                #pragma unroll 1
                for (int k = 0; k < 8; k++) {
                    wmma::fragment<wmma::matrix_a, 16, 16, 8, wmma::precision::tf32, wmma::row_major> a0, a1;
                    wmma::load_matrix_sync(a0, Xp + k * 8, HS3);
                    wmma::load_matrix_sync(a1, Xp + 16 * HS3 + k * 8, HS3);
                    #pragma unroll
                    for (int n = 0; n < 5; n++) {
                        wmma::fragment<wmma::matrix_b, 16, 16, 8, wmma::precision::tf32, wmma::row_major> bf;
                        wmma::load_matrix_sync(bf, S + OW2_3 + (k * 8) * W2S + 48 + n * 16, W2S);
                        wmma::mma_sync(c2[0][n], a0, bf, c2[0][n]);
                        wmma::mma_sync(c2[1][n], a1, bf, c2[1][n]);
                    }
                }
                __syncwarp();
                #pragma unroll
                for (int tt = 0; tt < 2; tt++)
                    #pragma unroll
                    for (int n = 0; n < 5; n++)
                        wmma::store_matrix_sync(Xp + tt * 16 * HS3 + n * 16, c2[tt][n], HS3, wmma::mem_row_major);
                __syncwarp();
                if (valid) {
                    #pragma unroll
                    for (int k = 0; k < 70; k++) {
                        int kd = k / 7;
                        omk[kd * 11 + 4 + (k - kd * 7)] = cr[k] + S[OB2_3 + 48 + k];
                    }
                }
            }
            __syncwarp();
        }
    }
}

// ================= motion wmma kernel (R11, committed) =================
#define MXS 52
#define MHS 68
#define OW1_M 0
#define OW2_M 3072
#define OB1R_M 6144
#define OB2R_M 7168
#define OWRP_M 7936
#define SLAB_M 1920
#define SMEMM_FLOATS (OWRP_M + 8 * SLAB_M)

__global__ __launch_bounds__(256, 2)
void mlp_mot_kernel(const float* __restrict__ xin,
                    const float* __restrict__ w1g, const float* __restrict__ b1g,
                    const float* __restrict__ w2g, const float* __restrict__ b2g,
                    const float* __restrict__ mfv,
                    float* __restrict__ out, int M)
{
    extern __shared__ float S[];
    const int tid = threadIdx.x;
    const int warp = tid >> 5;
    const int lane = tid & 31;

    for (int i = tid; i < 48 * 64; i += 256) S[OW1_M + i] = tf32r(w1g[i]);
    for (int i = tid; i < 64 * 48; i += 256) {
        int j = i / 48, k = i - j * 48;
        S[OW2_M + i] = (k < 37) ? tf32r(w2g[j * 37 + k]) : 0.f;
    }
    if (tid < 64) {
        float acc = b1g[tid];
        #pragma unroll
        for (int t = 0; t < 8; t++) {
            float ang = exp2f((float)t) * 1.5707963267948966f;
            acc = fmaf(sinf(ang), w1g[(48 + t) * 64 + tid], acc);
            acc = fmaf(cosf(ang), w1g[(56 + t) * 64 + tid], acc);
        }
        S[OB1R_M + tid] = acc;
    }
    if (tid < 48) S[OB2R_M + tid] = (tid < 37) ? b2g[tid] : 0.f;
    __syncthreads();
    for (int i = tid; i < 16 * 64; i += 256)
        if (i >= 64) S[OB1R_M + i] = S[OB1R_M + (i & 63)];
    for (int i = tid; i < 16 * 48; i += 256)
        if (i >= 48) S[OB2R_M + i] = S[OB2R_M + (i % 48)];
    __syncthreads();

    float* Xp = S + OWRP_M + warp * SLAB_M;
    float* Hp = Xp + 16 * MXS;
    const int tiles = (M + 15) >> 4;

    for (int t = blockIdx.x * 8 + warp; t < tiles; t += gridDim.x * 8) {
        {
            const float* src = xin + (size_t)t * 16 * 48;
            #pragma unroll
            for (int it = 0; it < 6; it++) {
                int e = lane * 4 + it * 128;
                float4 v = __ldg(reinterpret_cast<const float4*>(src + e));
                int row = e / 48, c = e - row * 48;
                *reinterpret_cast<float4*>(Xp + row * MXS + c) = v;
            }
        }
        __syncwarp();

        wmma::fragment<wmma::accumulator, 16, 16, 8, float> c1[4];
        #pragma unroll
        for (int n = 0; n < 4; n++)
            wmma::load_matrix_sync(c1[n], S + OB1R_M + n * 16, 64, wmma::mem_row_major);
        #pragma unroll 1
        for (int k = 0; k < 6; k++) {
            wmma::fragment<wmma::matrix_a, 16, 16, 8, wmma::precision::tf32, wmma::row_major> af;
            wmma::load_matrix_sync(af, Xp + k * 8, MXS);
            #pragma unroll
            for (int n = 0; n < 4; n++) {
                wmma::fragment<wmma::matrix_b, 16, 16, 8, wmma::precision::tf32, wmma::row_major> bf;
                wmma::load_matrix_sync(bf, S + OW1_M + k * 8 * 64 + n * 16, 64);
                wmma::mma_sync(c1[n], af, bf, c1[n]);
            }
        }
        #pragma unroll
        for (int n = 0; n < 4; n++) {
            #pragma unroll
            for (int i = 0; i < c1[n].num_elements; i++)
                c1[n].x[i] = tf32r(fmaxf(c1[n].x[i], 0.f));
            wmma::store_matrix_sync(Hp + n * 16, c1[n], MHS, wmma::mem_row_major);
        }
        __syncwarp();

        wmma::fragment<wmma::accumulator, 16, 16, 8, float> c2[3];
        #pragma unroll
        for (int n = 0; n < 3; n++)
            wmma::load_matrix_sync(c2[n], S + OB2R_M + n * 16, 48, wmma::mem_row_major);
        #pragma unroll 1
        for (int k = 0; k < 8; k++) {
            wmma::fragment<wmma::matrix_a, 16, 16, 8, wmma::precision::tf32, wmma::row_major> af;
            wmma::load_matrix_sync(af, Hp + k * 8, MHS);
            #pragma unroll
            for (int n = 0; n < 3; n++) {
                wmma::fragment<wmma::matrix_b, 16, 16, 8, wmma::precision::tf32, wmma::row_major> bf;
                wmma::load_matrix_sync(bf, S + OW2_M + k * 8 * 48 + n * 16, 48);
                wmma::mma_sync(c2[n], af, bf, c2[n]);
            }
        }
        __syncwarp();
        #pragma unroll
        for (int n = 0; n < 3; n++)
            wmma::store_matrix_sync(Xp + n * 16, c2[n], MXS, wmma::mem_row_major);
        __syncwarp();

        {
            int p = lane >> 1, half = lane & 1;
            size_t m = (size_t)t * 16 + p;
            if (m < (size_t)M) {
                float mfs = __ldg(mfv + m);
                float* om = out + (size_t)M * 110 + m * 50;
                const float* c2r = Xp + p * MXS;
                int k0 = half ? 19 : 0, k1 = half ? 37 : 19;
                for (int k = k0; k < k1; k++)
                    om[k] = c2r[k] * mfs;
            }
        }
        __syncwarp();
    }
}

// ================= launch =================
extern "C" void kernel_launch(void* const* d_in, const int* in_sizes, int n_in,
                              void* d_out, int out_size)
{
    const float* cam     = (const float*)d_in[0];
    const float* anchors = (const float*)d_in[1];
    const float* scales  = (const float*)d_in[2];
    const float* afeat   = (const float*)d_in[3];
    const float* tfeat   = (const float*)d_in[4];
    const float* factors = (const float*)d_in[5];
    const float* op_w1   = (const float*)d_in[6];
    const float* op_b1   = (const float*)d_in[7];
    const float* op_w2   = (const float*)d_in[8];
    const float* op_b2   = (const float*)d_in[9];
    const float* col_w1  = (const float*)d_in[10];
    const float* col_b1  = (const float*)d_in[11];
    const float* col_w2  = (const float*)d_in[12];
    const float* col_b2  = (const float*)d_in[13];
    const float* cov_w1  = (const float*)d_in[14];
    const float* cov_b1  = (const float*)d_in[15];
    const float* cov_w2  = (const float*)d_in[16];
    const float* cov_b2  = (const float*)d_in[17];
    const float* mot_w1  = (const float*)d_in[18];
    const float* mot_b1  = (const float*)d_in[19];
    const float* mot_w2  = (const float*)d_in[20];
    const float* mot_b2  = (const float*)d_in[21];
    const int*   vis     = (const int*)d_in[22];
    const int*   knn     = (const int*)d_in[23];

    int M = in_sizes[22];
    float* out = (float*)d_out;

    float *taf, *tafm, *pf, *mf;
    cudaGetSymbolAddress((void**)&taf,  g_taf);
    cudaGetSymbolAddress((void**)&tafm, g_tafm);
    cudaGetSymbolAddress((void**)&pf,   g_pf);
    cudaGetSymbolAddress((void**)&mf,   g_mf);

    const int GB = (M + 127) / 128;

    const int SMEM3 = SMEM3_FLOATS * 4;   // 228,352 B
    const int SMEMM = SMEMM_FLOATS * 4;
    cudaFuncSetAttribute(mlp3_kernel,    cudaFuncAttributeMaxDynamicSharedMemorySize, SMEM3);
    cudaFuncSetAttribute(mlp_mot_kernel, cudaFuncAttributeMaxDynamicSharedMemorySize, SMEMM);

    build_kernel<<<GB, 256>>>(cam, anchors, scales, afeat, tfeat, factors, vis, knn, out, M);
    mlp3_kernel<<<148, NT3, SMEM3>>>(
        taf,
        op_w1, op_b1, op_w2, op_b2,
        col_w1, col_b1, col_w2, col_b2,
        cov_w1, cov_b1, cov_w2, cov_b2,
        pf, out, M);
    mlp_mot_kernel<<<296, 256, SMEMM>>>(tafm, mot_w1, mot_b1, mot_w2, mot_b2, mf, out, M);
}